// round 15
// baseline (speedup 1.0000x reference)
#include <cuda_runtime.h>
#include <cuda_bf16.h>
#include <cuda_fp16.h>
#include <cuda_fp8.h>
#include <cstdint>

// EGCL_A2V — FP8 e4m3 mma.sync.m16n8k32 + ldmatrix, 192-row tiles,
// 12 warps as 6 pairs (M=32 x N=64 warp tiles). K=32 per mma: mma count and
// ldsm traffic both halved vs bf16. Epilogues fp32/f16x2; x1 bf16-packed.

#define NF 128
#define H  128
#define C  3
#define B_MAX 256
#define THREADS 384
#define NW 12
#define TILE 192
#define NBLK 148
#define PAD8 144                 // fp8 row stride (9*16B: ldsm conflict-free)
#define WIMG (128*PAD8)          // 18432 B per weight image
#define BSTEP8 (16*PAD8)

#define SMEM_SW 0                // 3*WIMG = 55296
#define SMEM_SA 55296            // 192*PAD8 = 27648
#define SMEM_F  82944
#define SMEM_TOTAL 108800

// float-region layout
#define F_WR    0
#define F_BE2   128
#define F_BC1   256
#define F_WC2   384
#define F_SRAD  512          // [192][3]
#define F_SDIFF 1088         // [192][9]
#define F_SSM2  2816         // [3][192][2] (slow path uses first 192)
#define F_SWP   3968         // [3][6][128]
#define F_SBID  6272         // int[192]

__device__ float g_V1[B_MAX * C * H];
__device__ float g_aggM[B_MAX * C * H];
__device__ float g_aggT[B_MAX * 9];
__device__ float g_cnt[B_MAX];
__device__ unsigned g_tile;
__device__ __align__(16) uint8_t g_Wimg[3 * WIMG];   // We1a^T, We2^T, Wc1^T e4m3 [n][k]

// ---------------- helpers ----------------
__device__ __forceinline__ float silu_p(float x) { return x / (1.0f + __expf(-x)); }

__device__ __forceinline__ float2 silu2(float f0, float f1) {
    __half2 h  = __floats2half2_rn(f0, f1);
    __half2 hx = __hmul2(h, __float2half2_rn(0.5f));
    uint32_t hu = *reinterpret_cast<uint32_t*>(&hx);
    uint32_t tu;
    asm("tanh.approx.f16x2 %0, %1;" : "=r"(tu) : "r"(hu));
    __half2 t = *reinterpret_cast<__half2*>(&tu);
    __half2 s = __hfma2(hx, t, hx);
    return __half22float2(s);
}
__device__ __forceinline__ uint32_t pack_bf16(float lo, float hi) {
    uint32_t r;
    asm("cvt.rn.bf16x2.f32 %0, %1, %2;" : "=r"(r) : "f"(hi), "f"(lo));
    return r;
}
__device__ __forceinline__ float2 unpack_bf16(uint32_t u) {
    __nv_bfloat162 h = *reinterpret_cast<__nv_bfloat162*>(&u);
    return __bfloat1622float2(h);
}
__device__ __forceinline__ uint16_t pack_e4m3x2(float lo, float hi) {
    uint16_t r;
    asm("cvt.rn.satfinite.e4m3x2.f32 %0, %1, %2;" : "=h"(r) : "f"(hi), "f"(lo));
    return r;
}
__device__ __forceinline__ float e4m3_f(uint8_t v) {
    __nv_fp8_e4m3 t;
    *reinterpret_cast<uint8_t*>(&t) = v;
    return (float)t;
}
__device__ __forceinline__ uint32_t smem_u32(const void* p) {
    uint32_t a;
    asm("{ .reg .u64 t; cvta.to.shared.u64 t, %1; cvt.u32.u64 %0, t; }" : "=r"(a) : "l"(p));
    return a;
}
__device__ __forceinline__ void ldsm_x4(uint32_t* r, uint32_t addr) {
    asm volatile("ldmatrix.sync.aligned.m8n8.x4.shared.b16 {%0,%1,%2,%3}, [%4];"
                 : "=r"(r[0]), "=r"(r[1]), "=r"(r[2]), "=r"(r[3]) : "r"(addr));
}
__device__ __forceinline__ void mma8(float* d,
        uint32_t a0, uint32_t a1, uint32_t a2, uint32_t a3,
        uint32_t b0, uint32_t b1) {
    asm volatile(
        "mma.sync.aligned.m16n8k32.row.col.f32.e4m3.e4m3.f32 "
        "{%0,%1,%2,%3}, {%4,%5,%6,%7}, {%8,%9}, {%0,%1,%2,%3};"
        : "+f"(d[0]), "+f"(d[1]), "+f"(d[2]), "+f"(d[3])
        : "r"(a0), "r"(a1), "r"(a2), "r"(a3), "r"(b0), "r"(b1));
}
__device__ __forceinline__ void bar_pair(int id) {
    asm volatile("bar.sync %0, 64;" :: "r"(id) : "memory");
}

// M=16 x N=128 fp8 GEMM (slow path): 4 ks x (1 A + 8 B ldsm, 16 mma)
__device__ __forceinline__ void gemm128_8(uint32_t aAddr, uint32_t bAddr, float* acc) {
#pragma unroll
    for (int ks = 0; ks < 4; ks++) {
        uint32_t A[4];
        ldsm_x4(A, aAddr + ks * 32);
#pragma unroll
        for (int ntp = 0; ntp < 8; ntp++) {
            uint32_t Bf[4];
            ldsm_x4(Bf, bAddr + ntp * BSTEP8 + ks * 32);
            mma8(acc + ntp * 8,     A[0], A[1], A[2], A[3], Bf[0], Bf[1]);
            mma8(acc + ntp * 8 + 4, A[0], A[1], A[2], A[3], Bf[2], Bf[3]);
        }
    }
}
// M=32 x N=64 fp8 GEMM (fast path): 4 ks x (2 A + 4 B ldsm, 16 mma)
__device__ __forceinline__ void gemm32x64_8(uint32_t aAddr, uint32_t bAddr, float* acc) {
#pragma unroll
    for (int ks = 0; ks < 4; ks++) {
        uint32_t A0[4], A1[4];
        ldsm_x4(A0, aAddr + ks * 32);
        ldsm_x4(A1, aAddr + 16 * PAD8 + ks * 32);
#pragma unroll
        for (int ntp = 0; ntp < 4; ntp++) {
            uint32_t Bf[4];
            ldsm_x4(Bf, bAddr + ntp * BSTEP8 + ks * 32);
            mma8(acc + (ntp * 2) * 4,          A0[0], A0[1], A0[2], A0[3], Bf[0], Bf[1]);
            mma8(acc + (ntp * 2 + 1) * 4,      A0[0], A0[1], A0[2], A0[3], Bf[2], Bf[3]);
            mma8(acc + 32 + (ntp * 2) * 4,     A1[0], A1[1], A1[2], A1[3], Bf[0], Bf[1]);
            mma8(acc + 32 + (ntp * 2 + 1) * 4, A1[0], A1[1], A1[2], A1[3], Bf[2], Bf[3]);
        }
    }
}

// ---------------------------------------------------------------------------
__global__ void prep_img(const float* __restrict__ We1,
                         const float* __restrict__ We2,
                         const float* __restrict__ Wc1,
                         uint8_t* __restrict__ gW) {
    int w = blockIdx.x >> 7, k = blockIdx.x & 127, n = threadIdx.x;
    const float* W = (w == 0) ? We1 : (w == 1) ? We2 : Wc1;
    __nv_fp8_e4m3 v(W[k * H + n]);
    gW[w * WIMG + n * PAD8 + k] = *reinterpret_cast<uint8_t*>(&v);
}

// ---------------------------------------------------------------------------
__global__ void prep_V1(const float* __restrict__ vnf,
                        const float* __restrict__ We1,
                        const float* __restrict__ be1) {
    __shared__ float sv[NF];
    int h = threadIdx.x, bc = blockIdx.x;
    int b = bc / C, c = bc % C;
    sv[h] = vnf[(b * NF + h) * C + c];
    __syncthreads();
    const float* w = We1 + NF * H;
    float a0 = 0.f, a1 = 0.f, a2 = 0.f, a3 = 0.f;
    float a4 = 0.f, a5 = 0.f, a6 = 0.f, a7 = 0.f;
#pragma unroll 4
    for (int f = 0; f < NF; f += 8) {
        a0 = fmaf(sv[f],     __ldg(&w[(f)     * H + h]), a0);
        a1 = fmaf(sv[f + 1], __ldg(&w[(f + 1) * H + h]), a1);
        a2 = fmaf(sv[f + 2], __ldg(&w[(f + 2) * H + h]), a2);
        a3 = fmaf(sv[f + 3], __ldg(&w[(f + 3) * H + h]), a3);
        a4 = fmaf(sv[f + 4], __ldg(&w[(f + 4) * H + h]), a4);
        a5 = fmaf(sv[f + 5], __ldg(&w[(f + 5) * H + h]), a5);
        a6 = fmaf(sv[f + 6], __ldg(&w[(f + 6) * H + h]), a6);
        a7 = fmaf(sv[f + 7], __ldg(&w[(f + 7) * H + h]), a7);
    }
    g_V1[bc * H + h] = be1[h] + (((a0 + a1) + (a2 + a3)) + ((a4 + a5) + (a6 + a7)));
    g_aggM[bc * H + h] = 0.0f;
    if (bc == 0) {
        for (int i = h; i < B_MAX * 9; i += blockDim.x) g_aggT[i] = 0.0f;
        for (int i = h; i < B_MAX; i += blockDim.x) g_cnt[i] = 0.0f;
        if (h == 0) g_tile = 0u;
    }
}

// ---------------------------------------------------------------------------
__global__ void __launch_bounds__(THREADS, 1)
main_kernel(const float* __restrict__ node_feat,
            const float* __restrict__ coord,
            const float* __restrict__ vcoord,
            const int*   __restrict__ batch,
            const float* __restrict__ We1,
            const float* __restrict__ be2,
            const float* __restrict__ bc1,
            const float* __restrict__ Wc2,
            int N) {
    extern __shared__ __align__(16) char smem[];
    uint8_t* sW = (uint8_t*)(smem + SMEM_SW);
    uint8_t* sA = (uint8_t*)(smem + SMEM_SA);
    float* sf = (float*)(smem + SMEM_F);
    float* swr   = sf + F_WR;
    float* sbe2  = sf + F_BE2;
    float* sbc1  = sf + F_BC1;
    float* swc2  = sf + F_WC2;
    float* srad  = sf + F_SRAD;
    float* sdiff = sf + F_SDIFF;
    float* ssm2  = sf + F_SSM2;
    float* swp   = sf + F_SWP;
    int*   sbid  = (int*)(sf + F_SBID);
    __shared__ int s_tile;

    const int tid = threadIdx.x, lane = tid & 31, warp = tid >> 5;
    const int mb = warp >> 1, nb = warp & 1;

    {   // weights -> smem (3*WIMG bytes)
        const uint4* src = (const uint4*)g_Wimg;
        uint4* dst = (uint4*)sW;
        for (int i = tid; i < 3 * WIMG / 16; i += THREADS) dst[i] = src[i];
    }
    if (tid < 128) {
        swr[tid]  = We1[256 * H + tid];
        sbe2[tid] = be2[tid];
        sbc1[tid] = bc1[tid];
        swc2[tid] = Wc2[tid];
    }
    __syncthreads();

    const uint32_t sA_u = smem_u32(sA);
    const uint32_t sW_u = smem_u32(sW);
    const uint32_t bRel =
        (((lane >> 4) & 1) * 8 + (lane & 7)) * PAD8 + ((lane >> 3) & 1) * 16;
    // slow-path (M=16) addressing
    const uint32_t aAddrS = sA_u + (warp * 16 + (lane & 15)) * PAD8 + (lane >> 4) * 16;
    const uint32_t bAddrS0 = sW_u + bRel;
    const uint32_t bAddrS1 = bAddrS0 + WIMG;
    const uint32_t bAddrS2 = bAddrS1 + WIMG;
    const int r0s = warp * 16 + (lane >> 2), r1s = r0s + 8;
    // fast-path (M=32 x N=64) addressing
    const uint32_t aAddrF = sA_u + (mb * 32 + (lane & 15)) * PAD8 + (lane >> 4) * 16;
    const uint32_t bAddrF0 = sW_u + bRel + (uint32_t)(nb * 64 * PAD8);
    const uint32_t bAddrF1 = bAddrF0 + WIMG;
    const uint32_t bAddrF2 = bAddrF1 + WIMG;
    const int rF = mb * 32 + (lane >> 2);      // + mf*16, +8

    const int ntiles = (N + TILE - 1) / TILE;
    for (;;) {
        if (tid == 0) s_tile = (int)atomicAdd(&g_tile, 1u);
        __syncthreads();                       // B1 (fences prev-tile agg too)
        const int t = s_tile;
        if (t >= ntiles) break;
        const int base = t * TILE;

        const bool tileFull = (base + TILE <= N);
        const int bFirst = __ldg(&batch[base]);
        const int bLast  = __ldg(&batch[min(base + TILE - 1, N - 1)]);
        const bool fast  = tileFull && (bFirst == bLast) && bFirst >= 0;
        const int b0t = bFirst < 0 ? 0 : bFirst;

        if (fast) {
            // ============ FAST PATH: pair-tiled M=32 x N=64 =================
            {   // own 16 rows: mb*32 + nb*16 + (lane>>1)
                int r = mb * 32 + nb * 16 + (lane >> 1), cb = (lane & 1) * 64;
                int n = base + r;
                const float4* nf = (const float4*)(node_feat + (size_t)n * NF + cb);
                uint8_t* dst = sA + r * PAD8 + cb;
#pragma unroll
                for (int q = 0; q < 16; q++) {
                    float4 v = __ldg(&nf[q]);
                    uint16_t h0 = pack_e4m3x2(v.x, v.y);
                    uint16_t h1 = pack_e4m3x2(v.z, v.w);
                    uint32_t u;
                    asm("mov.b32 %0, {%1,%2};" : "=r"(u) : "h"(h0), "h"(h1));
                    *(uint32_t*)(dst + q * 4) = u;
                }
                if (lane < 16) {
                    int m = mb * 32 + nb * 16 + lane, nn = base + m;
                    float cx = coord[nn * 3 + 0], cy = coord[nn * 3 + 1], cz = coord[nn * 3 + 2];
#pragma unroll
                    for (int cc = 0; cc < C; cc++) {
                        float dx = __ldg(&vcoord[(b0t * 3 + 0) * C + cc]) - cx;
                        float dy = __ldg(&vcoord[(b0t * 3 + 1) * C + cc]) - cy;
                        float dz = __ldg(&vcoord[(b0t * 3 + 2) * C + cc]) - cz;
                        sdiff[m * 9 + cc * 3 + 0] = dx;
                        sdiff[m * 9 + cc * 3 + 1] = dy;
                        sdiff[m * 9 + cc * 3 + 2] = dz;
                        srad[m * 3 + cc] = sqrtf(dx * dx + dy * dy + dz * dz);
                    }
                }
            }
            if (tid == 0) atomicAdd(&g_cnt[b0t], (float)TILE);
            bar_pair(mb + 1);                  // A rows + geometry ready

            // GEMM1 -> xp (packed bf16, acc layout)
            uint32_t xp[32];
            {
                float x1[64];
#pragma unroll
                for (int i = 0; i < 64; i++) x1[i] = 0.f;
                gemm32x64_8(aAddrF, bAddrF0, x1);
#pragma unroll
                for (int i = 0; i < 32; i++)
                    xp[i] = pack_bf16(x1[i * 2], x1[i * 2 + 1]);
            }
            bar_pair(mb + 1);                  // pair done reading sA(nf)

#pragma unroll 1
            for (int c = 0; c < C; c++) {
                const float* v1p = g_V1 + (b0t * C + c) * H;
                float radv[4];
#pragma unroll
                for (int mf = 0; mf < 2; mf++) {
                    radv[mf * 2 + 0] = srad[(rF + mf * 16) * 3 + c];
                    radv[mf * 2 + 1] = srad[(rF + mf * 16 + 8) * 3 + c];
                }

                // EpA: m1 -> sA (fp8, own 32 rows x 64 cols)
#pragma unroll
                for (int nt = 0; nt < 8; nt++) {
                    int c0 = nb * 64 + nt * 8 + (lane & 3) * 2;
                    float2 vv = __ldg((const float2*)(v1p + c0));
                    float w0 = swr[c0], w1 = swr[c0 + 1];
#pragma unroll
                    for (int mf = 0; mf < 2; mf++) {
                        int ib = mf * 16 + nt * 2;
                        float2 xv0 = unpack_bf16(xp[ib]);
                        float2 xv1 = unpack_bf16(xp[ib + 1]);
                        float2 u0 = silu2(xv0.x + vv.x + radv[mf * 2] * w0,
                                          xv0.y + vv.y + radv[mf * 2] * w1);
                        float2 u1 = silu2(xv1.x + vv.x + radv[mf * 2 + 1] * w0,
                                          xv1.y + vv.y + radv[mf * 2 + 1] * w1);
                        int rr = rF + mf * 16;
                        *(uint16_t*)(sA + rr * PAD8 + c0)       = pack_e4m3x2(u0.x, u0.y);
                        *(uint16_t*)(sA + (rr + 8) * PAD8 + c0) = pack_e4m3x2(u1.x, u1.y);
                    }
                }
                bar_pair(mb + 1);

                // GEMM2
                float acc[64];
#pragma unroll
                for (int i = 0; i < 64; i++) acc[i] = 0.f;
                gemm32x64_8(aAddrF, bAddrF1, acc);
                bar_pair(mb + 1);

                // EpB: m2 -> sA (fp8) + per-pair column sums -> swp[c][mb]
#pragma unroll
                for (int nt = 0; nt < 8; nt++) {
                    int c0 = nb * 64 + nt * 8 + (lane & 3) * 2;
                    float v0 = 0.f, v1 = 0.f;
#pragma unroll
                    for (int mf = 0; mf < 2; mf++) {
                        const float* a = acc + mf * 32 + nt * 4;
                        float2 u0 = silu2(a[0] + sbe2[c0], a[1] + sbe2[c0 + 1]);
                        float2 u1 = silu2(a[2] + sbe2[c0], a[3] + sbe2[c0 + 1]);
                        int rr = rF + mf * 16;
                        *(uint16_t*)(sA + rr * PAD8 + c0)       = pack_e4m3x2(u0.x, u0.y);
                        *(uint16_t*)(sA + (rr + 8) * PAD8 + c0) = pack_e4m3x2(u1.x, u1.y);
                        v0 += u0.x + u1.x;
                        v1 += u0.y + u1.y;
                    }
                    v0 += __shfl_xor_sync(0xffffffffu, v0, 4);
                    v0 += __shfl_xor_sync(0xffffffffu, v0, 8);
                    v0 += __shfl_xor_sync(0xffffffffu, v0, 16);
                    v1 += __shfl_xor_sync(0xffffffffu, v1, 4);
                    v1 += __shfl_xor_sync(0xffffffffu, v1, 8);
                    v1 += __shfl_xor_sync(0xffffffffu, v1, 16);
                    if (lane < 4) {
                        swp[(c * 6 + mb) * 128 + c0]     = v0;
                        swp[(c * 6 + mb) * 128 + c0 + 1] = v1;
                    }
                }
                bar_pair(mb + 1);

                // GEMM3
#pragma unroll
                for (int i = 0; i < 64; i++) acc[i] = 0.f;
                gemm32x64_8(aAddrF, bAddrF2, acc);

                // EpC: partial row scalars over own 64 cols
                {
                    float s00 = 0.f, s01 = 0.f, s10 = 0.f, s11 = 0.f;
#pragma unroll
                    for (int nt = 0; nt < 8; nt++) {
                        int c0 = nb * 64 + nt * 8 + (lane & 3) * 2;
                        float w0 = swc2[c0], w1 = swc2[c0 + 1];
                        {
                            const float* a = acc + nt * 4;
                            float2 u0 = silu2(a[0] + sbc1[c0], a[1] + sbc1[c0 + 1]);
                            float2 u1 = silu2(a[2] + sbc1[c0], a[3] + sbc1[c0 + 1]);
                            s00 += u0.x * w0 + u0.y * w1;
                            s01 += u1.x * w0 + u1.y * w1;
                        }
                        {
                            const float* a = acc + 32 + nt * 4;
                            float2 u0 = silu2(a[0] + sbc1[c0], a[1] + sbc1[c0 + 1]);
                            float2 u1 = silu2(a[2] + sbc1[c0], a[3] + sbc1[c0 + 1]);
                            s10 += u0.x * w0 + u0.y * w1;
                            s11 += u1.x * w0 + u1.y * w1;
                        }
                    }
                    s00 += __shfl_xor_sync(0xffffffffu, s00, 1);
                    s00 += __shfl_xor_sync(0xffffffffu, s00, 2);
                    s01 += __shfl_xor_sync(0xffffffffu, s01, 1);
                    s01 += __shfl_xor_sync(0xffffffffu, s01, 2);
                    s10 += __shfl_xor_sync(0xffffffffu, s10, 1);
                    s10 += __shfl_xor_sync(0xffffffffu, s10, 2);
                    s11 += __shfl_xor_sync(0xffffffffu, s11, 1);
                    s11 += __shfl_xor_sync(0xffffffffu, s11, 2);
                    if ((lane & 3) == 0) {
                        ssm2[c * 384 + (rF)      * 2 + nb] = s00;
                        ssm2[c * 384 + (rF + 8)  * 2 + nb] = s01;
                        ssm2[c * 384 + (rF + 16) * 2 + nb] = s10;
                        ssm2[c * 384 + (rF + 24) * 2 + nb] = s11;
                    }
                }
                bar_pair(mb + 1);   // partner GEMM3 done before next EpA write
            }

            __syncthreads();                   // B2: swp/ssm2/sdiff visible

            // aggM: 128 cols x 3 channels (6 pair partials)
            if (tid < 128) {
#pragma unroll
                for (int c = 0; c < C; c++) {
                    float s = 0.f;
#pragma unroll
                    for (int w = 0; w < 6; w++) s += swp[(c * 6 + w) * 128 + tid];
                    atomicAdd(&g_aggM[(b0t * C + c) * H + tid], s);
                }
            }
            // aggT: 9 (c,d) pairs by warps 0..8
            if (warp < 9) {
                int c = warp / 3, d = warp % 3;
                float v = 0.f;
#pragma unroll
                for (int q = 0; q < TILE / 32; q++) {
                    int r = lane + q * 32;
                    float sv = ssm2[c * 384 + r * 2] + ssm2[c * 384 + r * 2 + 1];
                    v += sdiff[r * 9 + c * 3 + d] * sv;
                }
                v += __shfl_xor_sync(0xffffffffu, v, 16);
                v += __shfl_xor_sync(0xffffffffu, v, 8);
                v += __shfl_xor_sync(0xffffffffu, v, 4);
                v += __shfl_xor_sync(0xffffffffu, v, 2);
                v += __shfl_xor_sync(0xffffffffu, v, 1);
                if (lane == 0) atomicAdd(&g_aggT[b0t * 9 + d * 3 + c], v);
            }
            continue;   // loop-top B1 fences agg reads
        }

        // ================= SLOW PATH (M=16 fp8) =============================
        if (tid < TILE) {
            int m = tid, n = base + m;
            bool valid = n < N;
            int nc = valid ? n : N - 1;
            int b = valid ? batch[n] : -1;
            sbid[m] = b;
            int bb = b < 0 ? 0 : b;
            float cx = coord[nc * 3 + 0], cy = coord[nc * 3 + 1], cz = coord[nc * 3 + 2];
#pragma unroll
            for (int cc = 0; cc < C; cc++) {
                float dx = __ldg(&vcoord[(bb * 3 + 0) * C + cc]) - cx;
                float dy = __ldg(&vcoord[(bb * 3 + 1) * C + cc]) - cy;
                float dz = __ldg(&vcoord[(bb * 3 + 2) * C + cc]) - cz;
                sdiff[m * 9 + cc * 3 + 0] = dx;
                sdiff[m * 9 + cc * 3 + 1] = dy;
                sdiff[m * 9 + cc * 3 + 2] = dz;
                srad[m * 3 + cc] = sqrtf(dx * dx + dy * dy + dz * dz);
            }
        }
        {
            int r = tid >> 1, cb = (tid & 1) * 64;
            int n = base + r;
            int nc = n < N ? n : N - 1;
            const float4* nf = (const float4*)(node_feat + (size_t)nc * NF + cb);
            uint8_t* dst = sA + r * PAD8 + cb;
#pragma unroll
            for (int q = 0; q < 16; q++) {
                float4 v = __ldg(&nf[q]);
                uint16_t h0 = pack_e4m3x2(v.x, v.y);
                uint16_t h1 = pack_e4m3x2(v.z, v.w);
                uint32_t u;
                asm("mov.b32 %0, {%1,%2};" : "=r"(u) : "h"(h0), "h"(h1));
                *(uint32_t*)(dst + q * 4) = u;
            }
        }
        __syncthreads();

        if (tid == 0) {
            int cb = sbid[0]; float cl = 0.f;
            for (int r = 0; r < TILE; r++) {
                int b2 = sbid[r];
                if (b2 != cb) { if (cb >= 0) atomicAdd(&g_cnt[cb], cl); cl = 0.f; cb = b2; }
                if (b2 >= 0) cl += 1.f;
            }
            if (cb >= 0) atomicAdd(&g_cnt[cb], cl);
        }

        int bb0 = sbid[r0s]; bb0 = bb0 < 0 ? 0 : bb0;
        int bb1 = sbid[r1s]; bb1 = bb1 < 0 ? 0 : bb1;

        uint32_t xp[32];
        {
            float x1[64];
#pragma unroll
            for (int i = 0; i < 64; i++) x1[i] = 0.f;
            gemm128_8(aAddrS, bAddrS0, x1);
#pragma unroll
            for (int i = 0; i < 32; i++)
                xp[i] = pack_bf16(x1[i * 2], x1[i * 2 + 1]);
        }
        __syncthreads();

#pragma unroll 1
        for (int c = 0; c < C; c++) {
            float rad0 = srad[r0s * 3 + c], rad1 = srad[r1s * 3 + c];
            const float* v0p = g_V1 + (bb0 * C + c) * H;
            const float* v1p = g_V1 + (bb1 * C + c) * H;
#pragma unroll
            for (int nt = 0; nt < 16; nt++) {
                int c0 = nt * 8 + (lane & 3) * 2;
                float2 xv0 = unpack_bf16(xp[nt * 2 + 0]);
                float2 xv1 = unpack_bf16(xp[nt * 2 + 1]);
                float w0 = swr[c0], w1 = swr[c0 + 1];
                float2 u0 = silu2(xv0.x + __ldg(&v0p[c0])     + rad0 * w0,
                                  xv0.y + __ldg(&v0p[c0 + 1]) + rad0 * w1);
                float2 u1 = silu2(xv1.x + __ldg(&v1p[c0])     + rad1 * w0,
                                  xv1.y + __ldg(&v1p[c0 + 1]) + rad1 * w1);
                *(uint16_t*)(sA + r0s * PAD8 + c0) = pack_e4m3x2(u0.x, u0.y);
                *(uint16_t*)(sA + r1s * PAD8 + c0) = pack_e4m3x2(u1.x, u1.y);
            }
            __syncthreads();

            float acc[64];
#pragma unroll
            for (int i = 0; i < 64; i++) acc[i] = 0.f;
            gemm128_8(aAddrS, bAddrS1, acc);
            __syncthreads();

#pragma unroll
            for (int nt = 0; nt < 16; nt++) {
                int c0 = nt * 8 + (lane & 3) * 2;
                float2 u0 = silu2(acc[nt * 4 + 0] + sbe2[c0], acc[nt * 4 + 1] + sbe2[c0 + 1]);
                float2 u1 = silu2(acc[nt * 4 + 2] + sbe2[c0], acc[nt * 4 + 3] + sbe2[c0 + 1]);
                *(uint16_t*)(sA + r0s * PAD8 + c0) = pack_e4m3x2(u0.x, u0.y);
                *(uint16_t*)(sA + r1s * PAD8 + c0) = pack_e4m3x2(u1.x, u1.y);
            }
            __syncthreads();

#pragma unroll
            for (int i = 0; i < 64; i++) acc[i] = 0.f;
            gemm128_8(aAddrS, bAddrS2, acc);

            {
                float s0 = 0.f, s1 = 0.f;
#pragma unroll
                for (int nt = 0; nt < 16; nt++) {
                    int c0 = nt * 8 + (lane & 3) * 2;
                    float2 u0 = silu2(acc[nt * 4 + 0] + sbc1[c0], acc[nt * 4 + 1] + sbc1[c0 + 1]);
                    float2 u1 = silu2(acc[nt * 4 + 2] + sbc1[c0], acc[nt * 4 + 3] + sbc1[c0 + 1]);
                    s0 += u0.x * swc2[c0] + u0.y * swc2[c0 + 1];
                    s1 += u1.x * swc2[c0] + u1.y * swc2[c0 + 1];
                }
                s0 += __shfl_xor_sync(0xffffffffu, s0, 1);
                s0 += __shfl_xor_sync(0xffffffffu, s0, 2);
                s1 += __shfl_xor_sync(0xffffffffu, s1, 1);
                s1 += __shfl_xor_sync(0xffffffffu, s1, 2);
                if ((lane & 3) == 0) { ssm2[r0s] = s0; ssm2[r1s] = s1; }
            }
            __syncthreads();

            if (tid < 128) {
                int col = tid; float a = 0.f; int cb = sbid[0];
                for (int r = 0; r < TILE; r++) {
                    int b2 = sbid[r];
                    if (b2 != cb) {
                        if (cb >= 0) atomicAdd(&g_aggM[(cb * C + c) * H + col], a);
                        a = 0.f; cb = b2;
                    }
                    if (b2 >= 0) a += e4m3_f(sA[r * PAD8 + col]);
                }
                if (cb >= 0) atomicAdd(&g_aggM[(cb * C + c) * H + col], a);
            }
            if (tid >= 128 && tid < 131) {
                int d = tid - 128; float a = 0.f; int cb = sbid[0];
                for (int r = 0; r < TILE; r++) {
                    int b2 = sbid[r];
                    if (b2 != cb) {
                        if (cb >= 0) atomicAdd(&g_aggT[cb * 9 + d * 3 + c], a);
                        a = 0.f; cb = b2;
                    }
                    if (b2 >= 0) a += sdiff[r * 9 + c * 3 + d] * ssm2[r];
                }
                if (cb >= 0) atomicAdd(&g_aggT[cb * 9 + d * 3 + c], a);
            }
            __syncthreads();
        }
    }
}

// ---------------------------------------------------------------------------
__global__ void final_kernel(const float* __restrict__ vnf,
                             const float* __restrict__ vcoord,
                             const float* __restrict__ Wn1, const float* __restrict__ bn1,
                             const float* __restrict__ Wn2, const float* __restrict__ bn2,
                             float* __restrict__ out, int B) {
    __shared__ float s_in[2 * H];
    __shared__ float s_h1[H];
    __shared__ float s_p[2 * H];
    int tid = threadIdx.x;
    int b = blockIdx.x / C, c = blockIdx.x % C;

    float cnt = fmaxf(g_cnt[b], 1.0f);
    if (tid < 128) {
        s_in[tid]       = vnf[(b * NF + tid) * C + c];
        s_in[128 + tid] = g_aggM[(b * C + c) * H + tid] / cnt;
    }
    __syncthreads();
    {
        int col = tid & 127, half = tid >> 7;
        const float* w  = Wn1 + half * 128 * H;
        const float* xi = s_in + half * 128;
        float a0 = 0.f, a1 = 0.f, a2 = 0.f, a3 = 0.f;
        float a4 = 0.f, a5 = 0.f, a6 = 0.f, a7 = 0.f;
#pragma unroll 16
        for (int k = 0; k < 128; k += 8) {
            a0 = fmaf(xi[k],     __ldg(&w[(k)     * H + col]), a0);
            a1 = fmaf(xi[k + 1], __ldg(&w[(k + 1) * H + col]), a1);
            a2 = fmaf(xi[k + 2], __ldg(&w[(k + 2) * H + col]), a2);
            a3 = fmaf(xi[k + 3], __ldg(&w[(k + 3) * H + col]), a3);
            a4 = fmaf(xi[k + 4], __ldg(&w[(k + 4) * H + col]), a4);
            a5 = fmaf(xi[k + 5], __ldg(&w[(k + 5) * H + col]), a5);
            a6 = fmaf(xi[k + 6], __ldg(&w[(k + 6) * H + col]), a6);
            a7 = fmaf(xi[k + 7], __ldg(&w[(k + 7) * H + col]), a7);
        }
        s_p[half * 128 + col] = (((a0 + a1) + (a2 + a3)) + ((a4 + a5) + (a6 + a7)));
    }
    __syncthreads();
    if (tid < 128) s_h1[tid] = silu_p(bn1[tid] + s_p[tid] + s_p[128 + tid]);
    __syncthreads();
    {
        int col = tid & 127, half = tid >> 7;
        const float* hi = s_h1 + half * 64;
        const float* w  = Wn2 + half * 64 * H;
        float a0 = 0.f, a1 = 0.f, a2 = 0.f, a3 = 0.f;
        float a4 = 0.f, a5 = 0.f, a6 = 0.f, a7 = 0.f;
#pragma unroll 8
        for (int k = 0; k < 64; k += 8) {
            a0 = fmaf(hi[k],     __ldg(&w[(k)     * H + col]), a0);
            a1 = fmaf(hi[k + 1], __ldg(&w[(k + 1) * H + col]), a1);
            a2 = fmaf(hi[k + 2], __ldg(&w[(k + 2) * H + col]), a2);
            a3 = fmaf(hi[k + 3], __ldg(&w[(k + 3) * H + col]), a3);
            a4 = fmaf(hi[k + 4], __ldg(&w[(k + 4) * H + col]), a4);
            a5 = fmaf(hi[k + 5], __ldg(&w[(k + 5) * H + col]), a5);
            a6 = fmaf(hi[k + 6], __ldg(&w[(k + 6) * H + col]), a6);
            a7 = fmaf(hi[k + 7], __ldg(&w[(k + 7) * H + col]), a7);
        }
        s_p[half * 128 + col] = (((a0 + a1) + (a2 + a3)) + ((a4 + a5) + (a6 + a7)));
    }
    __syncthreads();
    if (tid < 128)
        out[(b * NF + tid) * C + c] =
            vnf[(b * NF + tid) * C + c] + bn2[tid] + s_p[tid] + s_p[128 + tid];

    if (c == 0 && tid >= 128 && tid < 137) {
        int t = tid - 128;
        int d = t / 3, cc = t % 3;
        int idx = (b * 3 + d) * C + cc;
        out[B * NF * C + idx] = vcoord[idx] + g_aggT[idx] / cnt;
    }
}

// ---------------------------------------------------------------------------
extern "C" void kernel_launch(void* const* d_in, const int* in_sizes, int n_in,
                              void* d_out, int out_size) {
    const float* node_feat = (const float*)d_in[0];
    const float* coord     = (const float*)d_in[1];
    const float* vnf       = (const float*)d_in[2];
    const float* vcoord    = (const float*)d_in[3];
    const int*   batch     = (const int*)  d_in[4];
    const float* We1 = (const float*)d_in[5];
    const float* be1 = (const float*)d_in[6];
    const float* We2 = (const float*)d_in[7];
    const float* be2 = (const float*)d_in[8];
    const float* Wc1 = (const float*)d_in[9];
    const float* bc1 = (const float*)d_in[10];
    const float* Wc2 = (const float*)d_in[11];
    const float* Wn1 = (const float*)d_in[12];
    const float* bn1 = (const float*)d_in[13];
    const float* Wn2 = (const float*)d_in[14];
    const float* bn2 = (const float*)d_in[15];

    int N = in_sizes[0] / NF;
    int B = in_sizes[2] / (NF * C);

    cudaFuncSetAttribute(main_kernel,
                         cudaFuncAttributeMaxDynamicSharedMemorySize, SMEM_TOTAL);

    uint8_t* gW = nullptr;
    cudaGetSymbolAddress((void**)&gW, g_Wimg);

    prep_img<<<3 * 128, 128>>>(We1, We2, Wc1, gW);
    prep_V1<<<B * C, 128>>>(vnf, We1, be1);
    main_kernel<<<NBLK, THREADS, SMEM_TOTAL>>>(node_feat, coord, vcoord, batch,
                                               We1, be2, bc1, Wc2, N);
    final_kernel<<<B * C, 256>>>(vnf, vcoord, Wn1, bn1, Wn2, bn2,
                                 (float*)d_out, B);
}

// round 16
// speedup vs baseline: 1.1555x; 1.1555x over previous
#include <cuda_runtime.h>
#include <cuda_bf16.h>
#include <cuda_fp16.h>
#include <cstdint>

// EGCL_A2V — bf16 HMMA + ldmatrix, 192-row tiles, 12 warps as 6 pairs.
// Fast path: M=32 x N=64 warp tiles, software-pipelined GEMM (A double-buffer
// + B single-step prefetch: every ldsm lands >=4 mma before use), pair-local
// named barriers. Slow path: M=16 body.

#define NF 128
#define H  128
#define C  3
#define B_MAX 256
#define THREADS 384
#define NW 12
#define TILE 192
#define NBLK 148
#define PAD 136
#define WSTRIDE (128*PAD)
#define BSTEP (16 * PAD * 2)

#define SMEM_SW 0
#define SMEM_SA 104448
#define SMEM_F  156672
#define SMEM_TOTAL 193280

// float-region layout
#define F_WR    0
#define F_BE2   128
#define F_BC1   256
#define F_WC2   384
#define F_SRAD  512          // [192][3]
#define F_SDIFF 1088         // [192][9]
#define F_SSM2  2816         // [3][192][2] (slow path uses first 192)
#define F_SWP   3968         // [3][6][128]
#define F_SBID  6272         // int[192]

__device__ float g_V1[B_MAX * C * H];
__device__ float g_aggM[B_MAX * C * H];
__device__ float g_aggT[B_MAX * 9];
__device__ float g_cnt[B_MAX];
__device__ unsigned g_tile;
__device__ __align__(16) __nv_bfloat16 g_Wimg[3 * WSTRIDE];

// ---------------- helpers ----------------
__device__ __forceinline__ float silu_p(float x) { return x / (1.0f + __expf(-x)); }

__device__ __forceinline__ float2 silu2(float f0, float f1) {
    __half2 h  = __floats2half2_rn(f0, f1);
    __half2 hx = __hmul2(h, __float2half2_rn(0.5f));
    uint32_t hu = *reinterpret_cast<uint32_t*>(&hx);
    uint32_t tu;
    asm("tanh.approx.f16x2 %0, %1;" : "=r"(tu) : "r"(hu));
    __half2 t = *reinterpret_cast<__half2*>(&tu);
    __half2 s = __hfma2(hx, t, hx);
    return __half22float2(s);
}
__device__ __forceinline__ uint32_t pack_bf16(float lo, float hi) {
    uint32_t r;
    asm("cvt.rn.bf16x2.f32 %0, %1, %2;" : "=r"(r) : "f"(hi), "f"(lo));
    return r;
}
__device__ __forceinline__ float2 unpack_bf16(uint32_t u) {
    __nv_bfloat162 h = *reinterpret_cast<__nv_bfloat162*>(&u);
    return __bfloat1622float2(h);
}
__device__ __forceinline__ uint32_t smem_u32(const void* p) {
    uint32_t a;
    asm("{ .reg .u64 t; cvta.to.shared.u64 t, %1; cvt.u32.u64 %0, t; }" : "=r"(a) : "l"(p));
    return a;
}
__device__ __forceinline__ void ldsm_x4(uint32_t* r, uint32_t addr) {
    asm volatile("ldmatrix.sync.aligned.m8n8.x4.shared.b16 {%0,%1,%2,%3}, [%4];"
                 : "=r"(r[0]), "=r"(r[1]), "=r"(r[2]), "=r"(r[3]) : "r"(addr));
}
__device__ __forceinline__ void mma16816(float* d,
        uint32_t a0, uint32_t a1, uint32_t a2, uint32_t a3,
        uint32_t b0, uint32_t b1) {
    asm volatile(
        "mma.sync.aligned.m16n8k16.row.col.f32.bf16.bf16.f32 "
        "{%0,%1,%2,%3}, {%4,%5,%6,%7}, {%8,%9}, {%0,%1,%2,%3};"
        : "+f"(d[0]), "+f"(d[1]), "+f"(d[2]), "+f"(d[3])
        : "r"(a0), "r"(a1), "r"(a2), "r"(a3), "r"(b0), "r"(b1));
}
__device__ __forceinline__ void bar_pair(int id) {
    asm volatile("bar.sync %0, 64;" :: "r"(id) : "memory");
}

// M=16 GEMM (slow path)
__device__ __forceinline__ void gemm128(uint32_t aAddr, uint32_t bAddr, float* acc) {
#pragma unroll 2
    for (int ks = 0; ks < 8; ks++) {
        uint32_t A[4];
        ldsm_x4(A, aAddr + ks * 32);
#pragma unroll
        for (int ntp = 0; ntp < 8; ntp++) {
            uint32_t Bf[4];
            ldsm_x4(Bf, bAddr + ntp * BSTEP + ks * 32);
            mma16816(acc + ntp * 8,     A[0], A[1], A[2], A[3], Bf[0], Bf[1]);
            mma16816(acc + ntp * 8 + 4, A[0], A[1], A[2], A[3], Bf[2], Bf[3]);
        }
    }
}
// M=32 x N=64 GEMM (fast path), software-pipelined:
// A double-buffered one ks ahead; B prefetched one ntp ahead.
__device__ __forceinline__ void gemm32x64(uint32_t aAddr, uint32_t bAddr, float* acc) {
    uint32_t A0[4], A1[4], A0n[4], A1n[4], Bc[4], Bn[4];
    ldsm_x4(A0, aAddr);
    ldsm_x4(A1, aAddr + 16 * PAD * 2);
    ldsm_x4(Bc, bAddr);
#pragma unroll 2
    for (int ks = 0; ks < 8; ks++) {
        const int ksn = (ks < 7 ? ks + 1 : 7) * 32;
        ldsm_x4(A0n, aAddr + ksn);
        ldsm_x4(A1n, aAddr + 16 * PAD * 2 + ksn);
#pragma unroll
        for (int ntp = 0; ntp < 4; ntp++) {
            const uint32_t nextB = (ntp < 3)
                ? (bAddr + (ntp + 1) * BSTEP + ks * 32)
                : (bAddr + ksn);
            ldsm_x4(Bn, nextB);
            mma16816(acc + (ntp * 2) * 4,          A0[0], A0[1], A0[2], A0[3], Bc[0], Bc[1]);
            mma16816(acc + (ntp * 2 + 1) * 4,      A0[0], A0[1], A0[2], A0[3], Bc[2], Bc[3]);
            mma16816(acc + 32 + (ntp * 2) * 4,     A1[0], A1[1], A1[2], A1[3], Bc[0], Bc[1]);
            mma16816(acc + 32 + (ntp * 2 + 1) * 4, A1[0], A1[1], A1[2], A1[3], Bc[2], Bc[3]);
            Bc[0] = Bn[0]; Bc[1] = Bn[1]; Bc[2] = Bn[2]; Bc[3] = Bn[3];
        }
        A0[0] = A0n[0]; A0[1] = A0n[1]; A0[2] = A0n[2]; A0[3] = A0n[3];
        A1[0] = A1n[0]; A1[1] = A1n[1]; A1[2] = A1n[2]; A1[3] = A1n[3];
    }
}

// ---------------------------------------------------------------------------
__global__ void prep_img(const float* __restrict__ We1,
                         const float* __restrict__ We2,
                         const float* __restrict__ Wc1,
                         __nv_bfloat16* __restrict__ gW) {
    int w = blockIdx.x >> 7, k = blockIdx.x & 127, n = threadIdx.x;
    const float* W = (w == 0) ? We1 : (w == 1) ? We2 : Wc1;
    gW[w * WSTRIDE + n * PAD + k] = __float2bfloat16(W[k * H + n]);
}

// ---------------------------------------------------------------------------
__global__ void prep_V1(const float* __restrict__ vnf,
                        const float* __restrict__ We1,
                        const float* __restrict__ be1) {
    __shared__ float sv[NF];
    int h = threadIdx.x, bc = blockIdx.x;
    int b = bc / C, c = bc % C;
    sv[h] = vnf[(b * NF + h) * C + c];
    __syncthreads();
    const float* w = We1 + NF * H;
    float a0 = 0.f, a1 = 0.f, a2 = 0.f, a3 = 0.f;
    float a4 = 0.f, a5 = 0.f, a6 = 0.f, a7 = 0.f;
#pragma unroll 4
    for (int f = 0; f < NF; f += 8) {
        a0 = fmaf(sv[f],     __ldg(&w[(f)     * H + h]), a0);
        a1 = fmaf(sv[f + 1], __ldg(&w[(f + 1) * H + h]), a1);
        a2 = fmaf(sv[f + 2], __ldg(&w[(f + 2) * H + h]), a2);
        a3 = fmaf(sv[f + 3], __ldg(&w[(f + 3) * H + h]), a3);
        a4 = fmaf(sv[f + 4], __ldg(&w[(f + 4) * H + h]), a4);
        a5 = fmaf(sv[f + 5], __ldg(&w[(f + 5) * H + h]), a5);
        a6 = fmaf(sv[f + 6], __ldg(&w[(f + 6) * H + h]), a6);
        a7 = fmaf(sv[f + 7], __ldg(&w[(f + 7) * H + h]), a7);
    }
    g_V1[bc * H + h] = be1[h] + (((a0 + a1) + (a2 + a3)) + ((a4 + a5) + (a6 + a7)));
    g_aggM[bc * H + h] = 0.0f;
    if (bc == 0) {
        for (int i = h; i < B_MAX * 9; i += blockDim.x) g_aggT[i] = 0.0f;
        for (int i = h; i < B_MAX; i += blockDim.x) g_cnt[i] = 0.0f;
        if (h == 0) g_tile = 0u;
    }
}

// ---------------------------------------------------------------------------
__global__ void __launch_bounds__(THREADS, 1)
main_kernel(const float* __restrict__ node_feat,
            const float* __restrict__ coord,
            const float* __restrict__ vcoord,
            const int*   __restrict__ batch,
            const float* __restrict__ We1,
            const float* __restrict__ be2,
            const float* __restrict__ bc1,
            const float* __restrict__ Wc2,
            int N) {
    extern __shared__ __align__(16) char smem[];
    __nv_bfloat16* sW = (__nv_bfloat16*)(smem + SMEM_SW);
    __nv_bfloat16* sA = (__nv_bfloat16*)(smem + SMEM_SA);
    float* sf = (float*)(smem + SMEM_F);
    float* swr   = sf + F_WR;
    float* sbe2  = sf + F_BE2;
    float* sbc1  = sf + F_BC1;
    float* swc2  = sf + F_WC2;
    float* srad  = sf + F_SRAD;
    float* sdiff = sf + F_SDIFF;
    float* ssm2  = sf + F_SSM2;
    float* swp   = sf + F_SWP;
    int*   sbid  = (int*)(sf + F_SBID);
    __shared__ int s_tile;

    const int tid = threadIdx.x, lane = tid & 31, warp = tid >> 5;
    const int mb = warp >> 1, nb = warp & 1;

    {   // weights -> smem
        const uint4* src = (const uint4*)g_Wimg;
        uint4* dst = (uint4*)sW;
        for (int i = tid; i < 3 * WSTRIDE * 2 / 16; i += THREADS) dst[i] = src[i];
    }
    if (tid < 128) {
        swr[tid]  = We1[256 * H + tid];
        sbe2[tid] = be2[tid];
        sbc1[tid] = bc1[tid];
        swc2[tid] = Wc2[tid];
    }
    __syncthreads();

    const uint32_t sA_u = smem_u32(sA);
    const uint32_t sW_u = smem_u32(sW);
    const uint32_t bRel =
        (((((lane >> 4) & 1) * 8 + (lane & 7)) * PAD + ((lane >> 3) & 1) * 8) << 1);
    // slow-path (M=16) addressing
    const uint32_t aAddrS = sA_u +
        (((warp * 16 + (lane & 15)) * PAD + (lane >> 4) * 8) << 1);
    const uint32_t bAddrS0 = sW_u + bRel;
    const uint32_t bAddrS1 = bAddrS0 + WSTRIDE * 2;
    const uint32_t bAddrS2 = bAddrS1 + WSTRIDE * 2;
    const int r0s = warp * 16 + (lane >> 2), r1s = r0s + 8;
    // fast-path (M=32 x N=64) addressing
    const uint32_t aAddrF = sA_u +
        (((mb * 32 + (lane & 15)) * PAD + (lane >> 4) * 8) << 1);
    const uint32_t bAddrF0 = sW_u + bRel + (uint32_t)(nb * 64 * PAD * 2);
    const uint32_t bAddrF1 = bAddrF0 + WSTRIDE * 2;
    const uint32_t bAddrF2 = bAddrF1 + WSTRIDE * 2;
    const int rF = mb * 32 + (lane >> 2);      // + mf*16, +8

    const int ntiles = (N + TILE - 1) / TILE;
    for (;;) {
        if (tid == 0) s_tile = (int)atomicAdd(&g_tile, 1u);
        __syncthreads();                       // B1 (fences prev-tile agg too)
        const int t = s_tile;
        if (t >= ntiles) break;
        const int base = t * TILE;

        const bool tileFull = (base + TILE <= N);
        const int bFirst = __ldg(&batch[base]);
        const int bLast  = __ldg(&batch[min(base + TILE - 1, N - 1)]);
        const bool fast  = tileFull && (bFirst == bLast) && bFirst >= 0;
        const int b0t = bFirst < 0 ? 0 : bFirst;

        if (fast) {
            // ============ FAST PATH: pair-tiled M=32 x N=64 =================
            {   // own 16 rows: mb*32 + nb*16 + (lane>>1)
                int r = mb * 32 + nb * 16 + (lane >> 1), cb = (lane & 1) * 64;
                int n = base + r;
                const float4* nf = (const float4*)(node_feat + (size_t)n * NF + cb);
                __nv_bfloat16* dst = sA + r * PAD + cb;
#pragma unroll
                for (int q = 0; q < 16; q++) {
                    float4 v = __ldg(&nf[q]);
                    *(uint32_t*)(dst + q * 4)     = pack_bf16(v.x, v.y);
                    *(uint32_t*)(dst + q * 4 + 2) = pack_bf16(v.z, v.w);
                }
                if (lane < 16) {   // geometry for row mb*32 + nb*16 + lane
                    int m = mb * 32 + nb * 16 + lane, nn = base + m;
                    float cx = coord[nn * 3 + 0], cy = coord[nn * 3 + 1], cz = coord[nn * 3 + 2];
#pragma unroll
                    for (int cc = 0; cc < C; cc++) {
                        float dx = __ldg(&vcoord[(b0t * 3 + 0) * C + cc]) - cx;
                        float dy = __ldg(&vcoord[(b0t * 3 + 1) * C + cc]) - cy;
                        float dz = __ldg(&vcoord[(b0t * 3 + 2) * C + cc]) - cz;
                        sdiff[m * 9 + cc * 3 + 0] = dx;
                        sdiff[m * 9 + cc * 3 + 1] = dy;
                        sdiff[m * 9 + cc * 3 + 2] = dz;
                        srad[m * 3 + cc] = sqrtf(dx * dx + dy * dy + dz * dz);
                    }
                }
            }
            if (tid == 0) atomicAdd(&g_cnt[b0t], (float)TILE);
            bar_pair(mb + 1);                  // A rows + geometry ready

            // GEMM1 -> xp (packed bf16, acc layout)
            uint32_t xp[32];
            {
                float x1[64];
#pragma unroll
                for (int i = 0; i < 64; i++) x1[i] = 0.f;
                gemm32x64(aAddrF, bAddrF0, x1);
#pragma unroll
                for (int i = 0; i < 32; i++)
                    xp[i] = pack_bf16(x1[i * 2], x1[i * 2 + 1]);
            }
            bar_pair(mb + 1);                  // pair done reading sA(nf)

#pragma unroll 1
            for (int c = 0; c < C; c++) {
                const float* v1p = g_V1 + (b0t * C + c) * H;
                float radv[4];
#pragma unroll
                for (int mf = 0; mf < 2; mf++) {
                    radv[mf * 2 + 0] = srad[(rF + mf * 16) * 3 + c];
                    radv[mf * 2 + 1] = srad[(rF + mf * 16 + 8) * 3 + c];
                }

                // EpA: m1 -> sA (own 32 rows x 64 cols)
#pragma unroll
                for (int nt = 0; nt < 8; nt++) {
                    int c0 = nb * 64 + nt * 8 + (lane & 3) * 2;
                    float2 vv = __ldg((const float2*)(v1p + c0));
                    float w0 = swr[c0], w1 = swr[c0 + 1];
#pragma unroll
                    for (int mf = 0; mf < 2; mf++) {
                        int ib = mf * 16 + nt * 2;
                        float2 xv0 = unpack_bf16(xp[ib]);
                        float2 xv1 = unpack_bf16(xp[ib + 1]);
                        float2 u0 = silu2(xv0.x + vv.x + radv[mf * 2] * w0,
                                          xv0.y + vv.y + radv[mf * 2] * w1);
                        float2 u1 = silu2(xv1.x + vv.x + radv[mf * 2 + 1] * w0,
                                          xv1.y + vv.y + radv[mf * 2 + 1] * w1);
                        int rr = rF + mf * 16;
                        *(uint32_t*)(sA + rr * PAD + c0)       = pack_bf16(u0.x, u0.y);
                        *(uint32_t*)(sA + (rr + 8) * PAD + c0) = pack_bf16(u1.x, u1.y);
                    }
                }
                bar_pair(mb + 1);

                // GEMM2
                float acc[64];
#pragma unroll
                for (int i = 0; i < 64; i++) acc[i] = 0.f;
                gemm32x64(aAddrF, bAddrF1, acc);
                bar_pair(mb + 1);

                // EpB: m2 -> sA + per-pair column sums -> swp[c][mb]
#pragma unroll
                for (int nt = 0; nt < 8; nt++) {
                    int c0 = nb * 64 + nt * 8 + (lane & 3) * 2;
                    float v0 = 0.f, v1 = 0.f;
#pragma unroll
                    for (int mf = 0; mf < 2; mf++) {
                        const float* a = acc + mf * 32 + nt * 4;
                        float2 u0 = silu2(a[0] + sbe2[c0], a[1] + sbe2[c0 + 1]);
                        float2 u1 = silu2(a[2] + sbe2[c0], a[3] + sbe2[c0 + 1]);
                        int rr = rF + mf * 16;
                        *(uint32_t*)(sA + rr * PAD + c0)       = pack_bf16(u0.x, u0.y);
                        *(uint32_t*)(sA + (rr + 8) * PAD + c0) = pack_bf16(u1.x, u1.y);
                        v0 += u0.x + u1.x;
                        v1 += u0.y + u1.y;
                    }
                    v0 += __shfl_xor_sync(0xffffffffu, v0, 4);
                    v0 += __shfl_xor_sync(0xffffffffu, v0, 8);
                    v0 += __shfl_xor_sync(0xffffffffu, v0, 16);
                    v1 += __shfl_xor_sync(0xffffffffu, v1, 4);
                    v1 += __shfl_xor_sync(0xffffffffu, v1, 8);
                    v1 += __shfl_xor_sync(0xffffffffu, v1, 16);
                    if (lane < 4) {
                        swp[(c * 6 + mb) * 128 + c0]     = v0;
                        swp[(c * 6 + mb) * 128 + c0 + 1] = v1;
                    }
                }
                bar_pair(mb + 1);

                // GEMM3
#pragma unroll
                for (int i = 0; i < 64; i++) acc[i] = 0.f;
                gemm32x64(aAddrF, bAddrF2, acc);

                // EpC: partial row scalars over own 64 cols
                {
                    float s00 = 0.f, s01 = 0.f, s10 = 0.f, s11 = 0.f;
#pragma unroll
                    for (int nt = 0; nt < 8; nt++) {
                        int c0 = nb * 64 + nt * 8 + (lane & 3) * 2;
                        float w0 = swc2[c0], w1 = swc2[c0 + 1];
                        {
                            const float* a = acc + nt * 4;
                            float2 u0 = silu2(a[0] + sbc1[c0], a[1] + sbc1[c0 + 1]);
                            float2 u1 = silu2(a[2] + sbc1[c0], a[3] + sbc1[c0 + 1]);
                            s00 += u0.x * w0 + u0.y * w1;
                            s01 += u1.x * w0 + u1.y * w1;
                        }
                        {
                            const float* a = acc + 32 + nt * 4;
                            float2 u0 = silu2(a[0] + sbc1[c0], a[1] + sbc1[c0 + 1]);
                            float2 u1 = silu2(a[2] + sbc1[c0], a[3] + sbc1[c0 + 1]);
                            s10 += u0.x * w0 + u0.y * w1;
                            s11 += u1.x * w0 + u1.y * w1;
                        }
                    }
                    s00 += __shfl_xor_sync(0xffffffffu, s00, 1);
                    s00 += __shfl_xor_sync(0xffffffffu, s00, 2);
                    s01 += __shfl_xor_sync(0xffffffffu, s01, 1);
                    s01 += __shfl_xor_sync(0xffffffffu, s01, 2);
                    s10 += __shfl_xor_sync(0xffffffffu, s10, 1);
                    s10 += __shfl_xor_sync(0xffffffffu, s10, 2);
                    s11 += __shfl_xor_sync(0xffffffffu, s11, 1);
                    s11 += __shfl_xor_sync(0xffffffffu, s11, 2);
                    if ((lane & 3) == 0) {
                        ssm2[c * 384 + (rF)      * 2 + nb] = s00;
                        ssm2[c * 384 + (rF + 8)  * 2 + nb] = s01;
                        ssm2[c * 384 + (rF + 16) * 2 + nb] = s10;
                        ssm2[c * 384 + (rF + 24) * 2 + nb] = s11;
                    }
                }
                bar_pair(mb + 1);   // partner GEMM3 done before next EpA write
            }

            __syncthreads();                   // B2: swp/ssm2/sdiff visible

            // aggM: 128 cols x 3 channels (6 pair partials)
            if (tid < 128) {
#pragma unroll
                for (int c = 0; c < C; c++) {
                    float s = 0.f;
#pragma unroll
                    for (int w = 0; w < 6; w++) s += swp[(c * 6 + w) * 128 + tid];
                    atomicAdd(&g_aggM[(b0t * C + c) * H + tid], s);
                }
            }
            // aggT: 9 (c,d) pairs by warps 0..8
            if (warp < 9) {
                int c = warp / 3, d = warp % 3;
                float v = 0.f;
#pragma unroll
                for (int q = 0; q < TILE / 32; q++) {
                    int r = lane + q * 32;
                    float sv = ssm2[c * 384 + r * 2] + ssm2[c * 384 + r * 2 + 1];
                    v += sdiff[r * 9 + c * 3 + d] * sv;
                }
                v += __shfl_xor_sync(0xffffffffu, v, 16);
                v += __shfl_xor_sync(0xffffffffu, v, 8);
                v += __shfl_xor_sync(0xffffffffu, v, 4);
                v += __shfl_xor_sync(0xffffffffu, v, 2);
                v += __shfl_xor_sync(0xffffffffu, v, 1);
                if (lane == 0) atomicAdd(&g_aggT[b0t * 9 + d * 3 + c], v);
            }
            continue;   // loop-top B1 fences agg reads
        }

        // ================= SLOW PATH (M=16) =================================
        if (tid < TILE) {
            int m = tid, n = base + m;
            bool valid = n < N;
            int nc = valid ? n : N - 1;
            int b = valid ? batch[n] : -1;
            sbid[m] = b;
            int bb = b < 0 ? 0 : b;
            float cx = coord[nc * 3 + 0], cy = coord[nc * 3 + 1], cz = coord[nc * 3 + 2];
#pragma unroll
            for (int cc = 0; cc < C; cc++) {
                float dx = __ldg(&vcoord[(bb * 3 + 0) * C + cc]) - cx;
                float dy = __ldg(&vcoord[(bb * 3 + 1) * C + cc]) - cy;
                float dz = __ldg(&vcoord[(bb * 3 + 2) * C + cc]) - cz;
                sdiff[m * 9 + cc * 3 + 0] = dx;
                sdiff[m * 9 + cc * 3 + 1] = dy;
                sdiff[m * 9 + cc * 3 + 2] = dz;
                srad[m * 3 + cc] = sqrtf(dx * dx + dy * dy + dz * dz);
            }
        }
        {
            int r = tid >> 1, cb = (tid & 1) * 64;
            int n = base + r;
            int nc = n < N ? n : N - 1;
            const float4* nf = (const float4*)(node_feat + (size_t)nc * NF + cb);
            __nv_bfloat16* dst = sA + r * PAD + cb;
#pragma unroll
            for (int q = 0; q < 16; q++) {
                float4 v = __ldg(&nf[q]);
                *(uint32_t*)(dst + q * 4)     = pack_bf16(v.x, v.y);
                *(uint32_t*)(dst + q * 4 + 2) = pack_bf16(v.z, v.w);
            }
        }
        __syncthreads();

        if (tid == 0) {
            int cb = sbid[0]; float cl = 0.f;
            for (int r = 0; r < TILE; r++) {
                int b2 = sbid[r];
                if (b2 != cb) { if (cb >= 0) atomicAdd(&g_cnt[cb], cl); cl = 0.f; cb = b2; }
                if (b2 >= 0) cl += 1.f;
            }
            if (cb >= 0) atomicAdd(&g_cnt[cb], cl);
        }

        int bb0 = sbid[r0s]; bb0 = bb0 < 0 ? 0 : bb0;
        int bb1 = sbid[r1s]; bb1 = bb1 < 0 ? 0 : bb1;

        uint32_t xp[32];
        {
            float x1[64];
#pragma unroll
            for (int i = 0; i < 64; i++) x1[i] = 0.f;
            gemm128(aAddrS, bAddrS0, x1);
#pragma unroll
            for (int i = 0; i < 32; i++)
                xp[i] = pack_bf16(x1[i * 2], x1[i * 2 + 1]);
        }
        __syncthreads();

#pragma unroll 1
        for (int c = 0; c < C; c++) {
            float rad0 = srad[r0s * 3 + c], rad1 = srad[r1s * 3 + c];
            const float* v0p = g_V1 + (bb0 * C + c) * H;
            const float* v1p = g_V1 + (bb1 * C + c) * H;
#pragma unroll
            for (int nt = 0; nt < 16; nt++) {
                int c0 = nt * 8 + (lane & 3) * 2;
                float2 xv0 = unpack_bf16(xp[nt * 2 + 0]);
                float2 xv1 = unpack_bf16(xp[nt * 2 + 1]);
                float w0 = swr[c0], w1 = swr[c0 + 1];
                float2 u0 = silu2(xv0.x + __ldg(&v0p[c0])     + rad0 * w0,
                                  xv0.y + __ldg(&v0p[c0 + 1]) + rad0 * w1);
                float2 u1 = silu2(xv1.x + __ldg(&v1p[c0])     + rad1 * w0,
                                  xv1.y + __ldg(&v1p[c0 + 1]) + rad1 * w1);
                *(uint32_t*)(sA + r0s * PAD + c0) = pack_bf16(u0.x, u0.y);
                *(uint32_t*)(sA + r1s * PAD + c0) = pack_bf16(u1.x, u1.y);
            }
            __syncthreads();

            float acc[64];
#pragma unroll
            for (int i = 0; i < 64; i++) acc[i] = 0.f;
            gemm128(aAddrS, bAddrS1, acc);
            __syncthreads();

#pragma unroll
            for (int nt = 0; nt < 16; nt++) {
                int c0 = nt * 8 + (lane & 3) * 2;
                float2 u0 = silu2(acc[nt * 4 + 0] + sbe2[c0], acc[nt * 4 + 1] + sbe2[c0 + 1]);
                float2 u1 = silu2(acc[nt * 4 + 2] + sbe2[c0], acc[nt * 4 + 3] + sbe2[c0 + 1]);
                *(uint32_t*)(sA + r0s * PAD + c0) = pack_bf16(u0.x, u0.y);
                *(uint32_t*)(sA + r1s * PAD + c0) = pack_bf16(u1.x, u1.y);
            }
            __syncthreads();

#pragma unroll
            for (int i = 0; i < 64; i++) acc[i] = 0.f;
            gemm128(aAddrS, bAddrS2, acc);

            {
                float s0 = 0.f, s1 = 0.f;
#pragma unroll
                for (int nt = 0; nt < 16; nt++) {
                    int c0 = nt * 8 + (lane & 3) * 2;
                    float2 u0 = silu2(acc[nt * 4 + 0] + sbc1[c0], acc[nt * 4 + 1] + sbc1[c0 + 1]);
                    float2 u1 = silu2(acc[nt * 4 + 2] + sbc1[c0], acc[nt * 4 + 3] + sbc1[c0 + 1]);
                    s0 += u0.x * swc2[c0] + u0.y * swc2[c0 + 1];
                    s1 += u1.x * swc2[c0] + u1.y * swc2[c0 + 1];
                }
                s0 += __shfl_xor_sync(0xffffffffu, s0, 1);
                s0 += __shfl_xor_sync(0xffffffffu, s0, 2);
                s1 += __shfl_xor_sync(0xffffffffu, s1, 1);
                s1 += __shfl_xor_sync(0xffffffffu, s1, 2);
                if ((lane & 3) == 0) { ssm2[r0s] = s0; ssm2[r1s] = s1; }
            }
            __syncthreads();

            if (tid < 128) {
                int col = tid; float a = 0.f; int cb = sbid[0];
                for (int r = 0; r < TILE; r++) {
                    int b2 = sbid[r];
                    if (b2 != cb) {
                        if (cb >= 0) atomicAdd(&g_aggM[(cb * C + c) * H + col], a);
                        a = 0.f; cb = b2;
                    }
                    if (b2 >= 0) a += __bfloat162float(sA[r * PAD + col]);
                }
                if (cb >= 0) atomicAdd(&g_aggM[(cb * C + c) * H + col], a);
            }
            if (tid >= 128 && tid < 131) {
                int d = tid - 128; float a = 0.f; int cb = sbid[0];
                for (int r = 0; r < TILE; r++) {
                    int b2 = sbid[r];
                    if (b2 != cb) {
                        if (cb >= 0) atomicAdd(&g_aggT[cb * 9 + d * 3 + c], a);
                        a = 0.f; cb = b2;
                    }
                    if (b2 >= 0) a += sdiff[r * 9 + c * 3 + d] * ssm2[r];
                }
                if (cb >= 0) atomicAdd(&g_aggT[cb * 9 + d * 3 + c], a);
            }
            __syncthreads();
        }
    }
}

// ---------------------------------------------------------------------------
__global__ void final_kernel(const float* __restrict__ vnf,
                             const float* __restrict__ vcoord,
                             const float* __restrict__ Wn1, const float* __restrict__ bn1,
                             const float* __restrict__ Wn2, const float* __restrict__ bn2,
                             float* __restrict__ out, int B) {
    __shared__ float s_in[2 * H];
    __shared__ float s_h1[H];
    __shared__ float s_p[2 * H];
    int tid = threadIdx.x;
    int b = blockIdx.x / C, c = blockIdx.x % C;

    float cnt = fmaxf(g_cnt[b], 1.0f);
    if (tid < 128) {
        s_in[tid]       = vnf[(b * NF + tid) * C + c];
        s_in[128 + tid] = g_aggM[(b * C + c) * H + tid] / cnt;
    }
    __syncthreads();
    {
        int col = tid & 127, half = tid >> 7;
        const float* w  = Wn1 + half * 128 * H;
        const float* xi = s_in + half * 128;
        float a0 = 0.f, a1 = 0.f, a2 = 0.f, a3 = 0.f;
        float a4 = 0.f, a5 = 0.f, a6 = 0.f, a7 = 0.f;
#pragma unroll 16
        for (int k = 0; k < 128; k += 8) {
            a0 = fmaf(xi[k],     __ldg(&w[(k)     * H + col]), a0);
            a1 = fmaf(xi[k + 1], __ldg(&w[(k + 1) * H + col]), a1);
            a2 = fmaf(xi[k + 2], __ldg(&w[(k + 2) * H + col]), a2);
            a3 = fmaf(xi[k + 3], __ldg(&w[(k + 3) * H + col]), a3);
            a4 = fmaf(xi[k + 4], __ldg(&w[(k + 4) * H + col]), a4);
            a5 = fmaf(xi[k + 5], __ldg(&w[(k + 5) * H + col]), a5);
            a6 = fmaf(xi[k + 6], __ldg(&w[(k + 6) * H + col]), a6);
            a7 = fmaf(xi[k + 7], __ldg(&w[(k + 7) * H + col]), a7);
        }
        s_p[half * 128 + col] = (((a0 + a1) + (a2 + a3)) + ((a4 + a5) + (a6 + a7)));
    }
    __syncthreads();
    if (tid < 128) s_h1[tid] = silu_p(bn1[tid] + s_p[tid] + s_p[128 + tid]);
    __syncthreads();
    {
        int col = tid & 127, half = tid >> 7;
        const float* hi = s_h1 + half * 64;
        const float* w  = Wn2 + half * 64 * H;
        float a0 = 0.f, a1 = 0.f, a2 = 0.f, a3 = 0.f;
        float a4 = 0.f, a5 = 0.f, a6 = 0.f, a7 = 0.f;
#pragma unroll 8
        for (int k = 0; k < 64; k += 8) {
            a0 = fmaf(hi[k],     __ldg(&w[(k)     * H + col]), a0);
            a1 = fmaf(hi[k + 1], __ldg(&w[(k + 1) * H + col]), a1);
            a2 = fmaf(hi[k + 2], __ldg(&w[(k + 2) * H + col]), a2);
            a3 = fmaf(hi[k + 3], __ldg(&w[(k + 3) * H + col]), a3);
            a4 = fmaf(hi[k + 4], __ldg(&w[(k + 4) * H + col]), a4);
            a5 = fmaf(hi[k + 5], __ldg(&w[(k + 5) * H + col]), a5);
            a6 = fmaf(hi[k + 6], __ldg(&w[(k + 6) * H + col]), a6);
            a7 = fmaf(hi[k + 7], __ldg(&w[(k + 7) * H + col]), a7);
        }
        s_p[half * 128 + col] = (((a0 + a1) + (a2 + a3)) + ((a4 + a5) + (a6 + a7)));
    }
    __syncthreads();
    if (tid < 128)
        out[(b * NF + tid) * C + c] =
            vnf[(b * NF + tid) * C + c] + bn2[tid] + s_p[tid] + s_p[128 + tid];

    if (c == 0 && tid >= 128 && tid < 137) {
        int t = tid - 128;
        int d = t / 3, cc = t % 3;
        int idx = (b * 3 + d) * C + cc;
        out[B * NF * C + idx] = vcoord[idx] + g_aggT[idx] / cnt;
    }
}

// ---------------------------------------------------------------------------
extern "C" void kernel_launch(void* const* d_in, const int* in_sizes, int n_in,
                              void* d_out, int out_size) {
    const float* node_feat = (const float*)d_in[0];
    const float* coord     = (const float*)d_in[1];
    const float* vnf       = (const float*)d_in[2];
    const float* vcoord    = (const float*)d_in[3];
    const int*   batch     = (const int*)  d_in[4];
    const float* We1 = (const float*)d_in[5];
    const float* be1 = (const float*)d_in[6];
    const float* We2 = (const float*)d_in[7];
    const float* be2 = (const float*)d_in[8];
    const float* Wc1 = (const float*)d_in[9];
    const float* bc1 = (const float*)d_in[10];
    const float* Wc2 = (const float*)d_in[11];
    const float* Wn1 = (const float*)d_in[12];
    const float* bn1 = (const float*)d_in[13];
    const float* Wn2 = (const float*)d_in[14];
    const float* bn2 = (const float*)d_in[15];

    int N = in_sizes[0] / NF;
    int B = in_sizes[2] / (NF * C);

    cudaFuncSetAttribute(main_kernel,
                         cudaFuncAttributeMaxDynamicSharedMemorySize, SMEM_TOTAL);

    __nv_bfloat16* gW = nullptr;
    cudaGetSymbolAddress((void**)&gW, g_Wimg);

    prep_img<<<3 * 128, 128>>>(We1, We2, Wc1, gW);
    prep_V1<<<B * C, 128>>>(vnf, We1, be1);
    main_kernel<<<NBLK, THREADS, SMEM_TOTAL>>>(node_feat, coord, vcoord, batch,
                                               We1, be2, bc1, Wc2, N);
    final_kernel<<<B * C, 256>>>(vnf, vcoord, Wn1, bn1, Wn2, bn2,
                                 (float*)d_out, B);
}

// round 17
// speedup vs baseline: 1.3620x; 1.1787x over previous
#include <cuda_runtime.h>
#include <cuda_bf16.h>
#include <cuda_fp16.h>
#include <cstdint>

// EGCL_A2V — bf16 HMMA + ldmatrix. Work unit = 32-row pair-tile: each of the
// 6 warp-pairs per CTA is an independent worker with its own dynamic ticket.
// No __syncthreads in the main loop (pair-local named barriers only); agg
// sums go straight to global atomics from registers. M=32 x N=64 warp tiles
// with software-pipelined GEMM.

#define NF 128
#define H  128
#define C  3
#define B_MAX 256
#define THREADS 384
#define NBLK 148
#define PAD 136
#define WSTRIDE (128*PAD)
#define BSTEP (16 * PAD * 2)

#define SMEM_SW 0
#define SMEM_SA 104448            // 192*PAD*2 = 52224
#define SMEM_F  156672
#define SMEM_TOTAL 170496

// float-region layout
#define F_WR    0
#define F_BE2   128
#define F_BC1   256
#define F_WC2   384
#define F_SRAD  512          // [192][3]
#define F_SDIFF 1088         // [192][9]
#define F_SSM2  2816         // [192][2] (slow path)
#define F_SBID  3200         // int[192]
#define F_STILE 3392         // int[6]

__device__ float g_V1[B_MAX * C * H];
__device__ float g_aggM[B_MAX * C * H];
__device__ float g_aggT[B_MAX * 9];
__device__ float g_cnt[B_MAX];
__device__ unsigned g_tile;
__device__ __align__(16) __nv_bfloat16 g_Wimg[3 * WSTRIDE];

// ---------------- helpers ----------------
__device__ __forceinline__ float silu_p(float x) { return x / (1.0f + __expf(-x)); }

__device__ __forceinline__ float2 silu2(float f0, float f1) {
    __half2 h  = __floats2half2_rn(f0, f1);
    __half2 hx = __hmul2(h, __float2half2_rn(0.5f));
    uint32_t hu = *reinterpret_cast<uint32_t*>(&hx);
    uint32_t tu;
    asm("tanh.approx.f16x2 %0, %1;" : "=r"(tu) : "r"(hu));
    __half2 t = *reinterpret_cast<__half2*>(&tu);
    __half2 s = __hfma2(hx, t, hx);
    return __half22float2(s);
}
__device__ __forceinline__ uint32_t pack_bf16(float lo, float hi) {
    uint32_t r;
    asm("cvt.rn.bf16x2.f32 %0, %1, %2;" : "=r"(r) : "f"(hi), "f"(lo));
    return r;
}
__device__ __forceinline__ float2 unpack_bf16(uint32_t u) {
    __nv_bfloat162 h = *reinterpret_cast<__nv_bfloat162*>(&u);
    return __bfloat1622float2(h);
}
__device__ __forceinline__ uint32_t smem_u32(const void* p) {
    uint32_t a;
    asm("{ .reg .u64 t; cvta.to.shared.u64 t, %1; cvt.u32.u64 %0, t; }" : "=r"(a) : "l"(p));
    return a;
}
__device__ __forceinline__ void ldsm_x4(uint32_t* r, uint32_t addr) {
    asm volatile("ldmatrix.sync.aligned.m8n8.x4.shared.b16 {%0,%1,%2,%3}, [%4];"
                 : "=r"(r[0]), "=r"(r[1]), "=r"(r[2]), "=r"(r[3]) : "r"(addr));
}
__device__ __forceinline__ void mma16816(float* d,
        uint32_t a0, uint32_t a1, uint32_t a2, uint32_t a3,
        uint32_t b0, uint32_t b1) {
    asm volatile(
        "mma.sync.aligned.m16n8k16.row.col.f32.bf16.bf16.f32 "
        "{%0,%1,%2,%3}, {%4,%5,%6,%7}, {%8,%9}, {%0,%1,%2,%3};"
        : "+f"(d[0]), "+f"(d[1]), "+f"(d[2]), "+f"(d[3])
        : "r"(a0), "r"(a1), "r"(a2), "r"(a3), "r"(b0), "r"(b1));
}
__device__ __forceinline__ void bar_pair(int id) {
    asm volatile("bar.sync %0, 64;" :: "r"(id) : "memory");
}

// M=32 x N=64 GEMM, software-pipelined (A double-buffer + B prefetch)
__device__ __forceinline__ void gemm32x64(uint32_t aAddr, uint32_t bAddr, float* acc) {
    uint32_t A0[4], A1[4], A0n[4], A1n[4], Bc[4], Bn[4];
    ldsm_x4(A0, aAddr);
    ldsm_x4(A1, aAddr + 16 * PAD * 2);
    ldsm_x4(Bc, bAddr);
#pragma unroll 2
    for (int ks = 0; ks < 8; ks++) {
        const int ksn = (ks < 7 ? ks + 1 : 7) * 32;
        ldsm_x4(A0n, aAddr + ksn);
        ldsm_x4(A1n, aAddr + 16 * PAD * 2 + ksn);
#pragma unroll
        for (int ntp = 0; ntp < 4; ntp++) {
            const uint32_t nextB = (ntp < 3)
                ? (bAddr + (ntp + 1) * BSTEP + ks * 32)
                : (bAddr + ksn);
            ldsm_x4(Bn, nextB);
            mma16816(acc + (ntp * 2) * 4,          A0[0], A0[1], A0[2], A0[3], Bc[0], Bc[1]);
            mma16816(acc + (ntp * 2 + 1) * 4,      A0[0], A0[1], A0[2], A0[3], Bc[2], Bc[3]);
            mma16816(acc + 32 + (ntp * 2) * 4,     A1[0], A1[1], A1[2], A1[3], Bc[0], Bc[1]);
            mma16816(acc + 32 + (ntp * 2 + 1) * 4, A1[0], A1[1], A1[2], A1[3], Bc[2], Bc[3]);
            Bc[0] = Bn[0]; Bc[1] = Bn[1]; Bc[2] = Bn[2]; Bc[3] = Bn[3];
        }
        A0[0] = A0n[0]; A0[1] = A0n[1]; A0[2] = A0n[2]; A0[3] = A0n[3];
        A1[0] = A1n[0]; A1[1] = A1n[1]; A1[2] = A1n[2]; A1[3] = A1n[3];
    }
}

// ---------------------------------------------------------------------------
// prep: weight images (first 384 blocks) + V1/zeroing (next B*C blocks)
// ---------------------------------------------------------------------------
__global__ void prep_kernel(const float* __restrict__ We1,
                            const float* __restrict__ We2,
                            const float* __restrict__ Wc1,
                            const float* __restrict__ vnf,
                            const float* __restrict__ be1,
                            __nv_bfloat16* __restrict__ gW) {
    if (blockIdx.x < 384) {
        int w = blockIdx.x >> 7, k = blockIdx.x & 127, n = threadIdx.x;
        const float* W = (w == 0) ? We1 : (w == 1) ? We2 : Wc1;
        gW[w * WSTRIDE + n * PAD + k] = __float2bfloat16(W[k * H + n]);
        return;
    }
    __shared__ float sv[NF];
    int h = threadIdx.x, bc = blockIdx.x - 384;
    int b = bc / C, c = bc % C;
    sv[h] = vnf[(b * NF + h) * C + c];
    __syncthreads();
    const float* w = We1 + NF * H;
    float a0 = 0.f, a1 = 0.f, a2 = 0.f, a3 = 0.f;
    float a4 = 0.f, a5 = 0.f, a6 = 0.f, a7 = 0.f;
#pragma unroll 4
    for (int f = 0; f < NF; f += 8) {
        a0 = fmaf(sv[f],     __ldg(&w[(f)     * H + h]), a0);
        a1 = fmaf(sv[f + 1], __ldg(&w[(f + 1) * H + h]), a1);
        a2 = fmaf(sv[f + 2], __ldg(&w[(f + 2) * H + h]), a2);
        a3 = fmaf(sv[f + 3], __ldg(&w[(f + 3) * H + h]), a3);
        a4 = fmaf(sv[f + 4], __ldg(&w[(f + 4) * H + h]), a4);
        a5 = fmaf(sv[f + 5], __ldg(&w[(f + 5) * H + h]), a5);
        a6 = fmaf(sv[f + 6], __ldg(&w[(f + 6) * H + h]), a6);
        a7 = fmaf(sv[f + 7], __ldg(&w[(f + 7) * H + h]), a7);
    }
    g_V1[bc * H + h] = be1[h] + (((a0 + a1) + (a2 + a3)) + ((a4 + a5) + (a6 + a7)));
    g_aggM[bc * H + h] = 0.0f;
    if (bc == 0) {
        for (int i = h; i < B_MAX * 9; i += blockDim.x) g_aggT[i] = 0.0f;
        for (int i = h; i < B_MAX; i += blockDim.x) g_cnt[i] = 0.0f;
        if (h == 0) g_tile = 0u;
    }
}

// ---------------------------------------------------------------------------
__global__ void __launch_bounds__(THREADS, 1)
main_kernel(const float* __restrict__ node_feat,
            const float* __restrict__ coord,
            const float* __restrict__ vcoord,
            const int*   __restrict__ batch,
            const float* __restrict__ We1,
            const float* __restrict__ be2,
            const float* __restrict__ bc1,
            const float* __restrict__ Wc2,
            int N) {
    extern __shared__ __align__(16) char smem[];
    __nv_bfloat16* sW = (__nv_bfloat16*)(smem + SMEM_SW);
    __nv_bfloat16* sA = (__nv_bfloat16*)(smem + SMEM_SA);
    float* sf = (float*)(smem + SMEM_F);
    float* swr   = sf + F_WR;
    float* sbe2  = sf + F_BE2;
    float* sbc1  = sf + F_BC1;
    float* swc2  = sf + F_WC2;
    float* srad  = sf + F_SRAD;
    float* sdiff = sf + F_SDIFF;
    float* ssm2  = sf + F_SSM2;
    int*   sbid  = (int*)(sf + F_SBID);
    int*   s_tile = (int*)(sf + F_STILE);

    const int tid = threadIdx.x, lane = tid & 31, warp = tid >> 5;
    const int mb = warp >> 1, nb = warp & 1;
    const int barid = mb + 1;

    {   // weights -> smem
        const uint4* src = (const uint4*)g_Wimg;
        uint4* dst = (uint4*)sW;
        for (int i = tid; i < 3 * WSTRIDE * 2 / 16; i += THREADS) dst[i] = src[i];
    }
    if (tid < 128) {
        swr[tid]  = We1[256 * H + tid];
        sbe2[tid] = be2[tid];
        sbc1[tid] = bc1[tid];
        swc2[tid] = Wc2[tid];
    }
    __syncthreads();

    const uint32_t sA_u = smem_u32(sA);
    const uint32_t sW_u = smem_u32(sW);
    const uint32_t bRel =
        (((((lane >> 4) & 1) * 8 + (lane & 7)) * PAD + ((lane >> 3) & 1) * 8) << 1);
    const uint32_t aAddrF = sA_u +
        (((mb * 32 + (lane & 15)) * PAD + (lane >> 4) * 8) << 1);
    const uint32_t bAddrF0 = sW_u + bRel + (uint32_t)(nb * 64 * PAD * 2);
    const uint32_t bAddrF1 = bAddrF0 + WSTRIDE * 2;
    const uint32_t bAddrF2 = bAddrF1 + WSTRIDE * 2;
    const int rF = mb * 32 + (lane >> 2);      // slice row (+8/+16/+24)
    const int slice = mb * 32;

    const int nunits = (N + 31) >> 5;
    for (;;) {
        if (nb == 0 && lane == 0) s_tile[mb] = (int)atomicAdd(&g_tile, 1u);
        bar_pair(barid);                       // ticket visible; prev smem free
        const int t = s_tile[mb];
        if (t >= nunits) break;
        const int base = t << 5;

        const bool full = (base + 32 <= N);
        const int bFirst = __ldg(&batch[base]);
        const int bLast  = __ldg(&batch[min(base + 31, N - 1)]);
        const bool fast  = full && (bFirst == bLast) && bFirst >= 0;
        const int b0t = bFirst < 0 ? 0 : bFirst;

        // ---- load own 16 rows + geometry (both paths) ----
        {
            int ml = nb * 16 + (lane >> 1), cb = (lane & 1) * 64;
            int n = base + ml;
            int nc = min(n, N - 1);
            const float4* nf = (const float4*)(node_feat + (size_t)nc * NF + cb);
            __nv_bfloat16* dst = sA + (slice + ml) * PAD + cb;
#pragma unroll
            for (int q = 0; q < 16; q++) {
                float4 v = __ldg(&nf[q]);
                *(uint32_t*)(dst + q * 4)     = pack_bf16(v.x, v.y);
                *(uint32_t*)(dst + q * 4 + 2) = pack_bf16(v.z, v.w);
            }
            if (lane < 16) {
                int ml2 = nb * 16 + lane, nn = base + ml2;
                int bv = (nn < N) ? __ldg(&batch[nn]) : -1;
                sbid[slice + ml2] = bv;
                int bb = bv < 0 ? 0 : bv;
                int nc2 = min(nn, N - 1);
                float cx = coord[nc2 * 3 + 0], cy = coord[nc2 * 3 + 1], cz = coord[nc2 * 3 + 2];
#pragma unroll
                for (int cc = 0; cc < C; cc++) {
                    float dx = __ldg(&vcoord[(bb * 3 + 0) * C + cc]) - cx;
                    float dy = __ldg(&vcoord[(bb * 3 + 1) * C + cc]) - cy;
                    float dz = __ldg(&vcoord[(bb * 3 + 2) * C + cc]) - cz;
                    int m = slice + ml2;
                    sdiff[m * 9 + cc * 3 + 0] = dx;
                    sdiff[m * 9 + cc * 3 + 1] = dy;
                    sdiff[m * 9 + cc * 3 + 2] = dz;
                    srad[m * 3 + cc] = sqrtf(dx * dx + dy * dy + dz * dz);
                }
            }
        }
        if (nb == 0 && lane == 0) {
            if (fast) atomicAdd(&g_cnt[b0t], 32.f);
            else {
                int cb = sbid[slice]; float cl = 0.f;
                for (int r = 0; r < 32; r++) {
                    int b2 = sbid[slice + r];
                    if (b2 != cb) { if (cb >= 0) atomicAdd(&g_cnt[cb], cl); cl = 0.f; cb = b2; }
                    if (b2 >= 0) cl += 1.f;
                }
                if (cb >= 0) atomicAdd(&g_cnt[cb], cl);
            }
        }
        bar_pair(barid);                       // A rows + geometry + sbid ready

        // GEMM1 -> xp (packed bf16, acc layout)
        uint32_t xp[32];
        {
            float x1[64];
#pragma unroll
            for (int i = 0; i < 64; i++) x1[i] = 0.f;
            gemm32x64(aAddrF, bAddrF0, x1);
#pragma unroll
            for (int i = 0; i < 32; i++)
                xp[i] = pack_bf16(x1[i * 2], x1[i * 2 + 1]);
        }
        bar_pair(barid);                       // pair done reading sA(nf)

        if (fast) {
#pragma unroll 1
            for (int c = 0; c < C; c++) {
                const float* v1p = g_V1 + (b0t * C + c) * H;
                float radv[4];
#pragma unroll
                for (int mf = 0; mf < 2; mf++) {
                    radv[mf * 2 + 0] = srad[(rF + mf * 16) * 3 + c];
                    radv[mf * 2 + 1] = srad[(rF + mf * 16 + 8) * 3 + c];
                }
                // EpA
#pragma unroll
                for (int nt = 0; nt < 8; nt++) {
                    int c0 = nb * 64 + nt * 8 + (lane & 3) * 2;
                    float2 vv = __ldg((const float2*)(v1p + c0));
                    float w0 = swr[c0], w1 = swr[c0 + 1];
#pragma unroll
                    for (int mf = 0; mf < 2; mf++) {
                        int ib = mf * 16 + nt * 2;
                        float2 xv0 = unpack_bf16(xp[ib]);
                        float2 xv1 = unpack_bf16(xp[ib + 1]);
                        float2 u0 = silu2(xv0.x + vv.x + radv[mf * 2] * w0,
                                          xv0.y + vv.y + radv[mf * 2] * w1);
                        float2 u1 = silu2(xv1.x + vv.x + radv[mf * 2 + 1] * w0,
                                          xv1.y + vv.y + radv[mf * 2 + 1] * w1);
                        int rr = rF + mf * 16;
                        *(uint32_t*)(sA + rr * PAD + c0)       = pack_bf16(u0.x, u0.y);
                        *(uint32_t*)(sA + (rr + 8) * PAD + c0) = pack_bf16(u1.x, u1.y);
                    }
                }
                bar_pair(barid);

                // GEMM2
                float acc[64];
#pragma unroll
                for (int i = 0; i < 64; i++) acc[i] = 0.f;
                gemm32x64(aAddrF, bAddrF1, acc);
                bar_pair(barid);

                // EpB: m2 -> sA + direct aggM atomics
#pragma unroll
                for (int nt = 0; nt < 8; nt++) {
                    int c0 = nb * 64 + nt * 8 + (lane & 3) * 2;
                    float v0 = 0.f, v1 = 0.f;
#pragma unroll
                    for (int mf = 0; mf < 2; mf++) {
                        const float* a = acc + mf * 32 + nt * 4;
                        float2 u0 = silu2(a[0] + sbe2[c0], a[1] + sbe2[c0 + 1]);
                        float2 u1 = silu2(a[2] + sbe2[c0], a[3] + sbe2[c0 + 1]);
                        int rr = rF + mf * 16;
                        *(uint32_t*)(sA + rr * PAD + c0)       = pack_bf16(u0.x, u0.y);
                        *(uint32_t*)(sA + (rr + 8) * PAD + c0) = pack_bf16(u1.x, u1.y);
                        v0 += u0.x + u1.x;
                        v1 += u0.y + u1.y;
                    }
                    v0 += __shfl_xor_sync(0xffffffffu, v0, 4);
                    v0 += __shfl_xor_sync(0xffffffffu, v0, 8);
                    v0 += __shfl_xor_sync(0xffffffffu, v0, 16);
                    v1 += __shfl_xor_sync(0xffffffffu, v1, 4);
                    v1 += __shfl_xor_sync(0xffffffffu, v1, 8);
                    v1 += __shfl_xor_sync(0xffffffffu, v1, 16);
                    if (lane < 4) {
                        atomicAdd(&g_aggM[(b0t * C + c) * H + c0], v0);
                        atomicAdd(&g_aggM[(b0t * C + c) * H + c0 + 1], v1);
                    }
                }
                bar_pair(barid);

                // GEMM3
#pragma unroll
                for (int i = 0; i < 64; i++) acc[i] = 0.f;
                gemm32x64(aAddrF, bAddrF2, acc);

                // EpC + aggT (registers only)
                {
                    float s00 = 0.f, s01 = 0.f, s10 = 0.f, s11 = 0.f;
#pragma unroll
                    for (int nt = 0; nt < 8; nt++) {
                        int c0 = nb * 64 + nt * 8 + (lane & 3) * 2;
                        float w0 = swc2[c0], w1 = swc2[c0 + 1];
                        {
                            const float* a = acc + nt * 4;
                            float2 u0 = silu2(a[0] + sbc1[c0], a[1] + sbc1[c0 + 1]);
                            float2 u1 = silu2(a[2] + sbc1[c0], a[3] + sbc1[c0 + 1]);
                            s00 += u0.x * w0 + u0.y * w1;
                            s01 += u1.x * w0 + u1.y * w1;
                        }
                        {
                            const float* a = acc + 32 + nt * 4;
                            float2 u0 = silu2(a[0] + sbc1[c0], a[1] + sbc1[c0 + 1]);
                            float2 u1 = silu2(a[2] + sbc1[c0], a[3] + sbc1[c0 + 1]);
                            s10 += u0.x * w0 + u0.y * w1;
                            s11 += u1.x * w0 + u1.y * w1;
                        }
                    }
                    s00 += __shfl_xor_sync(0xffffffffu, s00, 1);
                    s00 += __shfl_xor_sync(0xffffffffu, s00, 2);
                    s01 += __shfl_xor_sync(0xffffffffu, s01, 1);
                    s01 += __shfl_xor_sync(0xffffffffu, s01, 2);
                    s10 += __shfl_xor_sync(0xffffffffu, s10, 1);
                    s10 += __shfl_xor_sync(0xffffffffu, s10, 2);
                    s11 += __shfl_xor_sync(0xffffffffu, s11, 1);
                    s11 += __shfl_xor_sync(0xffffffffu, s11, 2);
                    // aggT: lane&3 = d; rows rF(+8,+16,+24)
                    int d = lane & 3;
                    float v = 0.f;
                    if (d < 3) {
                        v = sdiff[(rF)      * 9 + c * 3 + d] * s00
                          + sdiff[(rF + 8)  * 9 + c * 3 + d] * s01
                          + sdiff[(rF + 16) * 9 + c * 3 + d] * s10
                          + sdiff[(rF + 24) * 9 + c * 3 + d] * s11;
                    }
                    v += __shfl_xor_sync(0xffffffffu, v, 4);
                    v += __shfl_xor_sync(0xffffffffu, v, 8);
                    v += __shfl_xor_sync(0xffffffffu, v, 16);
                    if (lane < 3) atomicAdd(&g_aggT[b0t * 9 + lane * 3 + c], v);
                }
                bar_pair(barid);   // partner GEMM3 done before next EpA write
            }
            continue;
        }

        // ================= SLOW PATH (pair-local, 32 rows) ==================
#pragma unroll 1
        for (int c = 0; c < C; c++) {
            // EpA: per-row V1 gather
#pragma unroll
            for (int mf = 0; mf < 2; mf++) {
                int rr = rF + mf * 16;
                int bA = sbid[rr];     bA = bA < 0 ? 0 : bA;
                int bB = sbid[rr + 8]; bB = bB < 0 ? 0 : bB;
                const float* vA = g_V1 + (bA * C + c) * H;
                const float* vB = g_V1 + (bB * C + c) * H;
                float radA = srad[rr * 3 + c], radB = srad[(rr + 8) * 3 + c];
#pragma unroll
                for (int nt = 0; nt < 8; nt++) {
                    int c0 = nb * 64 + nt * 8 + (lane & 3) * 2;
                    int ib = mf * 16 + nt * 2;
                    float2 xv0 = unpack_bf16(xp[ib]);
                    float2 xv1 = unpack_bf16(xp[ib + 1]);
                    float w0 = swr[c0], w1 = swr[c0 + 1];
                    float2 vvA = __ldg((const float2*)(vA + c0));
                    float2 vvB = __ldg((const float2*)(vB + c0));
                    float2 u0 = silu2(xv0.x + vvA.x + radA * w0, xv0.y + vvA.y + radA * w1);
                    float2 u1 = silu2(xv1.x + vvB.x + radB * w0, xv1.y + vvB.y + radB * w1);
                    *(uint32_t*)(sA + rr * PAD + c0)       = pack_bf16(u0.x, u0.y);
                    *(uint32_t*)(sA + (rr + 8) * PAD + c0) = pack_bf16(u1.x, u1.y);
                }
            }
            bar_pair(barid);

            float acc[64];
#pragma unroll
            for (int i = 0; i < 64; i++) acc[i] = 0.f;
            gemm32x64(aAddrF, bAddrF1, acc);
            bar_pair(barid);

            // EpB: m2 -> sA only
#pragma unroll
            for (int nt = 0; nt < 8; nt++) {
                int c0 = nb * 64 + nt * 8 + (lane & 3) * 2;
#pragma unroll
                for (int mf = 0; mf < 2; mf++) {
                    const float* a = acc + mf * 32 + nt * 4;
                    float2 u0 = silu2(a[0] + sbe2[c0], a[1] + sbe2[c0 + 1]);
                    float2 u1 = silu2(a[2] + sbe2[c0], a[3] + sbe2[c0 + 1]);
                    int rr = rF + mf * 16;
                    *(uint32_t*)(sA + rr * PAD + c0)       = pack_bf16(u0.x, u0.y);
                    *(uint32_t*)(sA + (rr + 8) * PAD + c0) = pack_bf16(u1.x, u1.y);
                }
            }
            bar_pair(barid);

#pragma unroll
            for (int i = 0; i < 64; i++) acc[i] = 0.f;
            gemm32x64(aAddrF, bAddrF2, acc);

            // EpC -> ssm2 per row
            {
                float s00 = 0.f, s01 = 0.f, s10 = 0.f, s11 = 0.f;
#pragma unroll
                for (int nt = 0; nt < 8; nt++) {
                    int c0 = nb * 64 + nt * 8 + (lane & 3) * 2;
                    float w0 = swc2[c0], w1 = swc2[c0 + 1];
                    {
                        const float* a = acc + nt * 4;
                        float2 u0 = silu2(a[0] + sbc1[c0], a[1] + sbc1[c0 + 1]);
                        float2 u1 = silu2(a[2] + sbc1[c0], a[3] + sbc1[c0 + 1]);
                        s00 += u0.x * w0 + u0.y * w1;
                        s01 += u1.x * w0 + u1.y * w1;
                    }
                    {
                        const float* a = acc + 32 + nt * 4;
                        float2 u0 = silu2(a[0] + sbc1[c0], a[1] + sbc1[c0 + 1]);
                        float2 u1 = silu2(a[2] + sbc1[c0], a[3] + sbc1[c0 + 1]);
                        s10 += u0.x * w0 + u0.y * w1;
                        s11 += u1.x * w0 + u1.y * w1;
                    }
                }
                s00 += __shfl_xor_sync(0xffffffffu, s00, 1);
                s00 += __shfl_xor_sync(0xffffffffu, s00, 2);
                s01 += __shfl_xor_sync(0xffffffffu, s01, 1);
                s01 += __shfl_xor_sync(0xffffffffu, s01, 2);
                s10 += __shfl_xor_sync(0xffffffffu, s10, 1);
                s10 += __shfl_xor_sync(0xffffffffu, s10, 2);
                s11 += __shfl_xor_sync(0xffffffffu, s11, 1);
                s11 += __shfl_xor_sync(0xffffffffu, s11, 2);
                if ((lane & 3) == 0) {
                    ssm2[(rF)      * 2 + nb] = s00;
                    ssm2[(rF + 8)  * 2 + nb] = s01;
                    ssm2[(rF + 16) * 2 + nb] = s10;
                    ssm2[(rF + 24) * 2 + nb] = s11;
                }
            }
            bar_pair(barid);

            // aggM segmented: 64 threads x 2 cols
            {
                int col = nb * 32 + lane;
#pragma unroll
                for (int half = 0; half < 2; half++) {
                    int cc = col + half * 64;
                    float a = 0.f; int cb = sbid[slice];
                    for (int r = 0; r < 32; r++) {
                        int b2 = sbid[slice + r];
                        if (b2 != cb) {
                            if (cb >= 0) atomicAdd(&g_aggM[(cb * C + c) * H + cc], a);
                            a = 0.f; cb = b2;
                        }
                        if (b2 >= 0) a += __bfloat162float(sA[(slice + r) * PAD + cc]);
                    }
                    if (cb >= 0) atomicAdd(&g_aggM[(cb * C + c) * H + cc], a);
                }
            }
            // aggT segmented: 3 threads of warp nb=0
            if (nb == 0 && lane < 3) {
                int d = lane; float a = 0.f; int cb = sbid[slice];
                for (int r = 0; r < 32; r++) {
                    int b2 = sbid[slice + r];
                    if (b2 != cb) {
                        if (cb >= 0) atomicAdd(&g_aggT[cb * 9 + d * 3 + c], a);
                        a = 0.f; cb = b2;
                    }
                    if (b2 >= 0) {
                        float sv = ssm2[(slice + r) * 2] + ssm2[(slice + r) * 2 + 1];
                        a += sdiff[(slice + r) * 9 + c * 3 + d] * sv;
                    }
                }
                if (cb >= 0) atomicAdd(&g_aggT[cb * 9 + d * 3 + c], a);
            }
            bar_pair(barid);   // sA/ssm2 reads done before next EpA
        }
    }
}

// ---------------------------------------------------------------------------
__global__ void final_kernel(const float* __restrict__ vnf,
                             const float* __restrict__ vcoord,
                             const float* __restrict__ Wn1, const float* __restrict__ bn1,
                             const float* __restrict__ Wn2, const float* __restrict__ bn2,
                             float* __restrict__ out, int B) {
    __shared__ float s_in[2 * H];
    __shared__ float s_h1[H];
    __shared__ float s_p[2 * H];
    int tid = threadIdx.x;
    int b = blockIdx.x / C, c = blockIdx.x % C;

    float cnt = fmaxf(g_cnt[b], 1.0f);
    if (tid < 128) {
        s_in[tid]       = vnf[(b * NF + tid) * C + c];
        s_in[128 + tid] = g_aggM[(b * C + c) * H + tid] / cnt;
    }
    __syncthreads();
    {
        int col = tid & 127, half = tid >> 7;
        const float* w  = Wn1 + half * 128 * H;
        const float* xi = s_in + half * 128;
        float a0 = 0.f, a1 = 0.f, a2 = 0.f, a3 = 0.f;
        float a4 = 0.f, a5 = 0.f, a6 = 0.f, a7 = 0.f;
#pragma unroll 16
        for (int k = 0; k < 128; k += 8) {
            a0 = fmaf(xi[k],     __ldg(&w[(k)     * H + col]), a0);
            a1 = fmaf(xi[k + 1], __ldg(&w[(k + 1) * H + col]), a1);
            a2 = fmaf(xi[k + 2], __ldg(&w[(k + 2) * H + col]), a2);
            a3 = fmaf(xi[k + 3], __ldg(&w[(k + 3) * H + col]), a3);
            a4 = fmaf(xi[k + 4], __ldg(&w[(k + 4) * H + col]), a4);
            a5 = fmaf(xi[k + 5], __ldg(&w[(k + 5) * H + col]), a5);
            a6 = fmaf(xi[k + 6], __ldg(&w[(k + 6) * H + col]), a6);
            a7 = fmaf(xi[k + 7], __ldg(&w[(k + 7) * H + col]), a7);
        }
        s_p[half * 128 + col] = (((a0 + a1) + (a2 + a3)) + ((a4 + a5) + (a6 + a7)));
    }
    __syncthreads();
    if (tid < 128) s_h1[tid] = silu_p(bn1[tid] + s_p[tid] + s_p[128 + tid]);
    __syncthreads();
    {
        int col = tid & 127, half = tid >> 7;
        const float* hi = s_h1 + half * 64;
        const float* w  = Wn2 + half * 64 * H;
        float a0 = 0.f, a1 = 0.f, a2 = 0.f, a3 = 0.f;
        float a4 = 0.f, a5 = 0.f, a6 = 0.f, a7 = 0.f;
#pragma unroll 8
        for (int k = 0; k < 64; k += 8) {
            a0 = fmaf(hi[k],     __ldg(&w[(k)     * H + col]), a0);
            a1 = fmaf(hi[k + 1], __ldg(&w[(k + 1) * H + col]), a1);
            a2 = fmaf(hi[k + 2], __ldg(&w[(k + 2) * H + col]), a2);
            a3 = fmaf(hi[k + 3], __ldg(&w[(k + 3) * H + col]), a3);
            a4 = fmaf(hi[k + 4], __ldg(&w[(k + 4) * H + col]), a4);
            a5 = fmaf(hi[k + 5], __ldg(&w[(k + 5) * H + col]), a5);
            a6 = fmaf(hi[k + 6], __ldg(&w[(k + 6) * H + col]), a6);
            a7 = fmaf(hi[k + 7], __ldg(&w[(k + 7) * H + col]), a7);
        }
        s_p[half * 128 + col] = (((a0 + a1) + (a2 + a3)) + ((a4 + a5) + (a6 + a7)));
    }
    __syncthreads();
    if (tid < 128)
        out[(b * NF + tid) * C + c] =
            vnf[(b * NF + tid) * C + c] + bn2[tid] + s_p[tid] + s_p[128 + tid];

    if (c == 0 && tid >= 128 && tid < 137) {
        int t = tid - 128;
        int d = t / 3, cc = t % 3;
        int idx = (b * 3 + d) * C + cc;
        out[B * NF * C + idx] = vcoord[idx] + g_aggT[idx] / cnt;
    }
}

// ---------------------------------------------------------------------------
extern "C" void kernel_launch(void* const* d_in, const int* in_sizes, int n_in,
                              void* d_out, int out_size) {
    const float* node_feat = (const float*)d_in[0];
    const float* coord     = (const float*)d_in[1];
    const float* vnf       = (const float*)d_in[2];
    const float* vcoord    = (const float*)d_in[3];
    const int*   batch     = (const int*)  d_in[4];
    const float* We1 = (const float*)d_in[5];
    const float* be1 = (const float*)d_in[6];
    const float* We2 = (const float*)d_in[7];
    const float* be2 = (const float*)d_in[8];
    const float* Wc1 = (const float*)d_in[9];
    const float* bc1 = (const float*)d_in[10];
    const float* Wc2 = (const float*)d_in[11];
    const float* Wn1 = (const float*)d_in[12];
    const float* bn1 = (const float*)d_in[13];
    const float* Wn2 = (const float*)d_in[14];
    const float* bn2 = (const float*)d_in[15];

    int N = in_sizes[0] / NF;
    int B = in_sizes[2] / (NF * C);

    cudaFuncSetAttribute(main_kernel,
                         cudaFuncAttributeMaxDynamicSharedMemorySize, SMEM_TOTAL);

    __nv_bfloat16* gW = nullptr;
    cudaGetSymbolAddress((void**)&gW, g_Wimg);

    prep_kernel<<<384 + B * C, 128>>>(We1, We2, Wc1, vnf, be1, gW);
    main_kernel<<<NBLK, THREADS, SMEM_TOTAL>>>(node_feat, coord, vcoord, batch,
                                               We1, be2, bc1, Wc2, N);
    final_kernel<<<B * C, 256>>>(vnf, vcoord, Wn1, bn1, Wn2, bn2,
                                 (float*)d_out, B);
}